// round 8
// baseline (speedup 1.0000x reference)
#include <cuda_runtime.h>
#include <cuda_bf16.h>
#include <cuda_fp16.h>
#include <stdint.h>
#include <math.h>

#define MTOT 50000
#define NE   800000

#if defined(__CUDA_ARCH_FEAT_SM103_ALL) || defined(__CUDA_ARCH_FEAT_SM100_ALL) || \
    defined(__CUDA_ARCH_FEAT_SM101_ALL) || defined(__CUDA_ARCH_FEAT_SM110_ALL)
#define TC_OK 1
#else
#define TC_OK 0
#endif

// ---------------- device scratch (no cudaMalloc) ----------------------------
__device__ __align__(16) float  g_yh[(size_t)MTOT * 256];   // fp16 view L1-4, fp32 L5
__device__ __align__(16) __half g_yxA[(size_t)MTOT * 256];
__device__ __align__(16) __half g_yxB[(size_t)MTOT * 256];
__device__ __align__(16) __half g_Whi[262144];
__device__ __align__(16) __half g_Wlo[262144];
__device__ float g_dinv[MTOT];
__device__ int   g_deg[MTOT];
__device__ int   g_off[MTOT + 1];
__device__ int   g_cur[MTOT];
__device__ int   g_csrc[NE];
__device__ int   g_bsum[64];

// ---------------- small helpers ---------------------------------------------
__device__ __forceinline__ uint32_t smem_u32(const void* p) {
    uint32_t a;
    asm("{ .reg .u64 t; cvta.to.shared.u64 t, %1; cvt.u32.u64 %0, t; }" : "=r"(a) : "l"(p));
    return a;
}
__device__ __forceinline__ bool elect1() {
    uint32_t p;
    asm volatile("{\n\t.reg .pred p;\n\telect.sync _|p, 0xFFFFFFFF;\n\tselp.b32 %0,1,0,p;\n\t}" : "=r"(p));
    return p != 0;
}
__device__ __forceinline__ void mbar_init(uint32_t mbar, uint32_t cnt) {
    asm volatile("mbarrier.init.shared.b64 [%0], %1;" :: "r"(mbar), "r"(cnt) : "memory");
}
__device__ __forceinline__ void mbar_wait(uint32_t mbar, uint32_t parity) {
    uint32_t done;
    asm volatile("{\n\t.reg .pred p;\n\tmbarrier.try_wait.parity.acquire.cta.shared::cta.b64 p, [%1], %2;\n\tselp.b32 %0,1,0,p;\n\t}"
                 : "=r"(done) : "r"(mbar), "r"(parity) : "memory");
    if (!done) {
        asm volatile("{\n\t.reg .pred P1;\nWL_%=:\n\tmbarrier.try_wait.parity.acquire.cta.shared::cta.b64 P1, [%0], %1, 0x989680;\n\t@P1 bra.uni WD_%=;\n\tbra.uni WL_%=;\nWD_%=:\n\t}"
                     :: "r"(mbar), "r"(parity) : "memory");
    }
}
__device__ __forceinline__ float tanha(float x) {
    float y; asm("tanh.approx.f32 %0, %1;" : "=f"(y) : "f"(x)); return y;
}
__device__ __forceinline__ uint32_t pkh2(float a, float b) {
    __half2 h = __floats2half2_rn(a, b);
    return *reinterpret_cast<uint32_t*>(&h);
}

#if TC_OK
__device__ __forceinline__ uint64_t mk_desc(uint32_t addr) {
    // SW128, version=1(Blackwell), SBO=64, LBO=1, start=addr>>4
    return 0x4000404000010000ULL | ((uint64_t)(addr >> 4) & 0x3FFF);
}
__device__ __forceinline__ void mma_ss_f16(uint32_t d, uint64_t ad, uint64_t bd,
                                           uint32_t idesc, uint32_t en) {
    asm volatile("{\n\t.reg .pred p;\n\tsetp.ne.u32 p, %4, 0;\n\t"
                 "tcgen05.mma.cta_group::1.kind::f16 [%0], %1, %2, %3, {%5,%5,%5,%5}, p;\n\t}"
                 :: "r"(d), "l"(ad), "l"(bd), "r"(idesc), "r"(en), "r"(0u) : "memory");
}
#define LDTM32(r, addr) \
    asm volatile("tcgen05.ld.sync.aligned.32x32b.x32.b32 " \
        "{%0,%1,%2,%3,%4,%5,%6,%7,%8,%9,%10,%11,%12,%13,%14,%15," \
        "%16,%17,%18,%19,%20,%21,%22,%23,%24,%25,%26,%27,%28,%29,%30,%31}, [%32];" \
        : "=r"((r)[0]),"=r"((r)[1]),"=r"((r)[2]),"=r"((r)[3]),"=r"((r)[4]),"=r"((r)[5]),"=r"((r)[6]),"=r"((r)[7]), \
          "=r"((r)[8]),"=r"((r)[9]),"=r"((r)[10]),"=r"((r)[11]),"=r"((r)[12]),"=r"((r)[13]),"=r"((r)[14]),"=r"((r)[15]), \
          "=r"((r)[16]),"=r"((r)[17]),"=r"((r)[18]),"=r"((r)[19]),"=r"((r)[20]),"=r"((r)[21]),"=r"((r)[22]),"=r"((r)[23]), \
          "=r"((r)[24]),"=r"((r)[25]),"=r"((r)[26]),"=r"((r)[27]),"=r"((r)[28]),"=r"((r)[29]),"=r"((r)[30]),"=r"((r)[31]) \
        : "r"(addr))
#endif

// ---------------- CSR build (parallel scan) ----------------------------------
__global__ void k_count(const int* __restrict__ dst) {
    int e = blockIdx.x * blockDim.x + threadIdx.x;
    if (e < NE) atomicAdd(&g_deg[dst[e]], 1);
}
__global__ void k_scan1() {
    __shared__ int sh[1024];
    int t = threadIdx.x;
    int i = blockIdx.x * 1024 + t;
    int v = (i < MTOT) ? g_deg[i] : 0;
    sh[t] = v;
    __syncthreads();
    for (int ofs = 1; ofs < 1024; ofs <<= 1) {
        int x = (t >= ofs) ? sh[t - ofs] : 0;
        __syncthreads();
        sh[t] += x;
        __syncthreads();
    }
    if (i < MTOT) g_off[i] = sh[t] - v;
    if (t == 1023) g_bsum[blockIdx.x] = sh[1023];
}
__global__ void k_scan2(int nblk) {
    __shared__ int sh[64];
    int t = threadIdx.x;
    int v = (t < nblk) ? g_bsum[t] : 0;
    sh[t] = v;
    __syncthreads();
    for (int ofs = 1; ofs < 64; ofs <<= 1) {
        int x = (t >= ofs) ? sh[t - ofs] : 0;
        __syncthreads();
        sh[t] += x;
        __syncthreads();
    }
    if (t < nblk) g_bsum[t] = sh[t] - v;
}
__global__ void k_scan3() {
    int i = blockIdx.x * 1024 + threadIdx.x;
    if (i < MTOT) {
        int o = g_off[i] + g_bsum[i >> 10];
        g_off[i] = o;
        g_cur[i] = o;
        int d = g_deg[i];
        g_dinv[i] = (d > 0) ? rsqrtf((float)d) : 0.0f;
    }
    if (i == 0) g_off[MTOT] = NE;
}
__global__ void k_scatter(const int* __restrict__ src, const int* __restrict__ dst) {
    int e = blockIdx.x * blockDim.x + threadIdx.x;
    if (e < NE) {
        int p = atomicAdd(&g_cur[dst[e]], 1);
        g_csrc[p] = src[e];
    }
}

// ---------------- weight converter -------------------------------------------
__global__ void k_convW2(const float* __restrict__ W, int F, int N,
                         __half* __restrict__ oh, __half* __restrict__ ol) {
    int idx = blockIdx.x * blockDim.x + threadIdx.x;
    if (idx >= 2 * F * N) return;
    int k2 = idx / N, n = idx % N;
    int half = (k2 >= F);
    int k = k2 - half * F;
    float v = W[(size_t)k2 * N + n];
    __half h = __float2half_rn(v);
    size_t o = (size_t)half * N * F + (size_t)n * F + k;
    oh[o] = h;
    ol[o] = __float2half_rn(v - __half2float(h));
}

// ---------------- fused layer kernel -----------------------------------------
// MODE 0: A-tile from x (fp32, K=128, convert). MODE 1: A-tile = tanh(yh - dv*Σyx[j]).
// Then dual-output tcgen05 GEMM: yh' = A@Wh + b (TMEM [0,256)); yx' = dv*(A@Wx).
// SMEM: A chunks (K/64)x16KB @0; B 2 bufs x 64KB @64K/@128K.
template <int MODE>
__global__ void __launch_bounds__(256, 1) k_fused(
    const float* __restrict__ xin,
    const __half* __restrict__ yx_in, const __half* __restrict__ yh_in,
    int K, const __half* __restrict__ Whi, const __half* __restrict__ Wlo,
    const float* __restrict__ bias, int Nout, uint32_t idesc,
    __half* __restrict__ yh16_out, float* __restrict__ yhf32_out,
    __half* __restrict__ yx_out)
{
    extern __shared__ char smraw[];
    __shared__ __align__(16) uint32_t ctrl[8];
    int tid = threadIdx.x, wid = tid >> 5, lane = tid & 31;
    uint32_t raw = smem_u32(smraw);
    uint32_t sb = (raw + 1023) & ~1023u;
    char* sm = smraw + (sb - raw);
    int m0 = blockIdx.x * 128;

#if TC_OK
    uint32_t cu = smem_u32(ctrl);
    if (wid == 0) {
        asm volatile("tcgen05.alloc.cta_group::1.sync.aligned.shared::cta.b32 [%0], %1;"
                     :: "r"(cu), "r"(512u) : "memory");
        asm volatile("tcgen05.relinquish_alloc_permit.cta_group::1.sync.aligned;");
    }
    if (tid == 0) { mbar_init(cu + 8, 1); mbar_init(cu + 16, 1); }
#endif

    // ---- prologue: build swizzled A tile in SMEM ----
    if constexpr (MODE == 0) {
        // lane covers cols [4*lane, 4*lane+4) of K=128; chunk = lane>>4
        for (int it = 0; it < 16; it++) {
            int row = wid * 16 + it;
            int node = m0 + row;
            uint2 hp = make_uint2(0, 0);
            if (node < MTOT) {
                float4 v = *reinterpret_cast<const float4*>(xin + (size_t)node * 128 + lane * 4);
                hp.x = pkh2(v.x, v.y);
                hp.y = pkh2(v.z, v.w);
            }
            uint32_t bo = (row << 7) + ((lane * 8) & 127);
            uint32_t so = bo ^ ((bo >> 3) & 0x70);
            *reinterpret_cast<uint2*>(sm + (lane >> 4) * 16384 + so) = hp;
        }
    } else {
        // lane covers cols [8*lane, 8*lane+8) of K=256; chunk = lane>>3
        const char* yxb = (const char*)yx_in;
        const char* yhb = (const char*)yh_in;
        for (int it = 0; it < 16; it++) {
            int row = wid * 16 + it;
            int node = m0 + row;
            uint4 hp = make_uint4(0, 0, 0, 0);
            if (node < MTOT) {
                float acc[8];
#pragma unroll
                for (int i = 0; i < 8; i++) acc[i] = 0.f;
                int e0 = g_off[node], e1 = g_off[node + 1];
                float dv = g_dinv[node];
                size_t lofs = (size_t)lane * 16;
                int e = e0;
                for (; e + 8 <= e1; e += 8) {
                    uint4 P[8];
#pragma unroll
                    for (int u = 0; u < 8; u++) {
                        int j = g_csrc[e + u];
                        P[u] = *reinterpret_cast<const uint4*>(yxb + (size_t)j * 512 + lofs);
                    }
#pragma unroll
                    for (int u = 0; u < 8; u++) {
                        uint32_t w[4] = {P[u].x, P[u].y, P[u].z, P[u].w};
#pragma unroll
                        for (int q = 0; q < 4; q++) {
                            float2 f = __half22float2(*reinterpret_cast<__half2*>(&w[q]));
                            acc[2 * q] += f.x;
                            acc[2 * q + 1] += f.y;
                        }
                    }
                }
                for (; e < e1; e++) {
                    int j = g_csrc[e];
                    uint4 p = *reinterpret_cast<const uint4*>(yxb + (size_t)j * 512 + lofs);
                    uint32_t w[4] = {p.x, p.y, p.z, p.w};
#pragma unroll
                    for (int q = 0; q < 4; q++) {
                        float2 f = __half22float2(*reinterpret_cast<__half2*>(&w[q]));
                        acc[2 * q] += f.x;
                        acc[2 * q + 1] += f.y;
                    }
                }
                uint4 y = *reinterpret_cast<const uint4*>(yhb + (size_t)node * 512 + lofs);
                uint32_t yw[4] = {y.x, y.y, y.z, y.w};
                float v[8];
#pragma unroll
                for (int q = 0; q < 4; q++) {
                    float2 f = __half22float2(*reinterpret_cast<__half2*>(&yw[q]));
                    v[2 * q]     = tanha(f.x - dv * acc[2 * q]);
                    v[2 * q + 1] = tanha(f.y - dv * acc[2 * q + 1]);
                }
                hp.x = pkh2(v[0], v[1]); hp.y = pkh2(v[2], v[3]);
                hp.z = pkh2(v[4], v[5]); hp.w = pkh2(v[6], v[7]);
            }
            uint32_t bo = (row << 7) + ((lane * 16) & 127);
            uint32_t so = bo ^ ((bo >> 3) & 0x70);
            *reinterpret_cast<uint4*>(sm + (lane >> 3) * 16384 + so) = hp;
        }
    }

#if TC_OK
    __syncthreads();  // A-tile + tmem ptr visible
    uint32_t tmem;
    asm("ld.shared.b32 %0, [%1];" : "=r"(tmem) : "r"(cu));

    int NS = (K >> 6) * 2;
    int nbB = Nout << 3;
    int loOfs = Nout << 7;

    for (int s = 0; s < NS; s++) {
        int kc = s >> 1, out = s & 1, buf = s & 1;
        char* bst = sm + 65536 + buf * 65536;
        uint32_t bstu = sb + 65536 + buf * 65536;
        if (s >= 2) mbar_wait(cu + 8 + buf * 8, ((s >> 1) - 1) & 1);

        {
            size_t wofs = (size_t)out * Nout * K;
            const char* Bh = (const char*)(Whi + wofs);
            const char* Bl = (const char*)(Wlo + wofs);
            for (int i = tid; i < nbB; i += 256) {
                int n = i >> 3, c = i & 7;
                size_t go = ((size_t)n * K + (kc << 6) + (c << 3)) * 2;
                uint4 vh = *reinterpret_cast<const uint4*>(Bh + go);
                uint4 vl = *reinterpret_cast<const uint4*>(Bl + go);
                uint32_t bo = (n << 7) + (c << 4);
                uint32_t so = bo ^ ((bo >> 3) & 0x70);
                *reinterpret_cast<uint4*>(bst + so) = vh;
                *reinterpret_cast<uint4*>(bst + loOfs + so) = vl;
            }
        }
        asm volatile("fence.proxy.async.shared::cta;" ::: "memory");
        __syncthreads();

        if (wid == 0 && elect1()) {
            uint64_t dA  = mk_desc(sb + kc * 16384);
            uint64_t dBh = mk_desc(bstu);
            uint64_t dBl = mk_desc(bstu + loOfs);
            uint32_t D = tmem + out * 256;
#pragma unroll
            for (int k = 0; k < 4; k++) {
                uint64_t o = (uint64_t)(k * 2);
                mma_ss_f16(D, dA + o, dBh + o, idesc, (uint32_t)((kc | k) != 0));
                mma_ss_f16(D, dA + o, dBl + o, idesc, 1u);
            }
            asm volatile("tcgen05.commit.cta_group::1.mbarrier::arrive::one.shared::cluster.b64 [%0];"
                         :: "r"(cu + 8 + buf * 8) : "memory");
        }
    }

    mbar_wait(cu + 8 + ((NS - 2) & 1) * 8, ((NS - 2) >> 1) & 1);
    mbar_wait(cu + 8 + ((NS - 1) & 1) * 8, ((NS - 1) >> 1) & 1);
    asm volatile("tcgen05.fence::after_thread_sync;" ::: "memory");

    int sub = wid & 3, wg = wid >> 2;
    int m = m0 + sub * 32 + lane;
    int niter = Nout >> 5;
    uint32_t base = tmem + wg * 256;
    for (int cc = 0; cc < niter; cc++) {
        uint32_t r[32];
        LDTM32(r, base + cc * 32);
        asm volatile("tcgen05.wait::ld.sync.aligned;" ::: "memory");
        if (m < MTOT) {
            int nb = cc * 32;
            if (wg == 0) {
                if (yh16_out) {
                    uint32_t hp[16];
#pragma unroll
                    for (int q = 0; q < 16; q++)
                        hp[q] = pkh2(__uint_as_float(r[2 * q])     + bias[nb + 2 * q],
                                     __uint_as_float(r[2 * q + 1]) + bias[nb + 2 * q + 1]);
                    uint4* dp = reinterpret_cast<uint4*>((char*)yh16_out + ((size_t)m * Nout + nb) * 2);
#pragma unroll
                    for (int q = 0; q < 4; q++)
                        dp[q] = make_uint4(hp[4 * q], hp[4 * q + 1], hp[4 * q + 2], hp[4 * q + 3]);
                } else {
                    float4* dp = reinterpret_cast<float4*>(yhf32_out + (size_t)m * Nout + nb);
#pragma unroll
                    for (int q = 0; q < 8; q++) {
                        float4 v;
                        v.x = __uint_as_float(r[q * 4 + 0]) + bias[nb + q * 4 + 0];
                        v.y = __uint_as_float(r[q * 4 + 1]) + bias[nb + q * 4 + 1];
                        v.z = __uint_as_float(r[q * 4 + 2]) + bias[nb + q * 4 + 2];
                        v.w = __uint_as_float(r[q * 4 + 3]) + bias[nb + q * 4 + 3];
                        dp[q] = v;
                    }
                }
            } else {
                float dv = g_dinv[m];
                uint32_t hp[16];
#pragma unroll
                for (int q = 0; q < 16; q++)
                    hp[q] = pkh2(dv * __uint_as_float(r[2 * q]),
                                 dv * __uint_as_float(r[2 * q + 1]));
                uint4* dp = reinterpret_cast<uint4*>((char*)yx_out + ((size_t)m * Nout + nb) * 2);
#pragma unroll
                for (int q = 0; q < 4; q++)
                    dp[q] = make_uint4(hp[4 * q], hp[4 * q + 1], hp[4 * q + 2], hp[4 * q + 3]);
            }
        }
    }
    __syncthreads();
    if (wid == 0) {
        asm volatile("tcgen05.dealloc.cta_group::1.sync.aligned.b32 %0, %1;"
                     :: "r"(tmem), "r"(512u));
    }
#else
    // SIMT fallback (non-"a" passes): naive GEMM from the SMEM A tile.
    __syncthreads();
    for (int idx = tid; idx < 128 * Nout; idx += 256) {
        int row = idx / Nout, n = idx % Nout;
        int m = m0 + row;
        if (m >= MTOT) continue;
        float s0 = 0.f, s1 = 0.f;
        for (int k = 0; k < K; k++) {
            uint32_t bo = (row << 7) + (k & 63) * 2;
            uint32_t so = bo ^ ((bo >> 3) & 0x70);
            float a = __half2float(*reinterpret_cast<const __half*>(sm + (k >> 6) * 16384 + so));
            size_t o = (size_t)n * K + k;
            float wh = __half2float(Whi[o]) + __half2float(Wlo[o]);
            float wx = __half2float(Whi[(size_t)Nout * K + o]) + __half2float(Wlo[(size_t)Nout * K + o]);
            s0 += a * wh;
            s1 += a * wx;
        }
        float v0 = s0 + bias[n];
        if (yh16_out) yh16_out[(size_t)m * Nout + n] = __float2half_rn(v0);
        else          yhf32_out[(size_t)m * Nout + n] = v0;
        yx_out[(size_t)m * Nout + n] = __float2half_rn(g_dinv[m] * s1);
    }
#endif
}

// ---------------- final aggregation (fp32 out, no tanh) ----------------------
__global__ void k_aggF(const float* __restrict__ yh, const __half* __restrict__ yx,
                       float* __restrict__ out) {
    int node = blockIdx.x * 8 + (threadIdx.x >> 5);
    if (node >= MTOT) return;
    int lane = threadIdx.x & 31;
    int col = lane * 4;
    float acc[4] = {0.f, 0.f, 0.f, 0.f};
    int e0 = g_off[node], e1 = g_off[node + 1];
    const char* yxb = (const char*)yx;
    int e = e0;
    for (; e + 4 <= e1; e += 4) {
        int j0 = g_csrc[e], j1 = g_csrc[e + 1], j2 = g_csrc[e + 2], j3 = g_csrc[e + 3];
        uint2 p0 = *reinterpret_cast<const uint2*>(yxb + ((size_t)j0 * 128 + col) * 2);
        uint2 p1 = *reinterpret_cast<const uint2*>(yxb + ((size_t)j1 * 128 + col) * 2);
        uint2 p2 = *reinterpret_cast<const uint2*>(yxb + ((size_t)j2 * 128 + col) * 2);
        uint2 p3 = *reinterpret_cast<const uint2*>(yxb + ((size_t)j3 * 128 + col) * 2);
        uint32_t w0[2] = {p0.x, p0.y};
        uint32_t w1[2] = {p1.x, p1.y};
        uint32_t w2[2] = {p2.x, p2.y};
        uint32_t w3[2] = {p3.x, p3.y};
#pragma unroll
        for (int q = 0; q < 2; q++) {
            float2 f0 = __half22float2(*reinterpret_cast<__half2*>(&w0[q]));
            float2 f1 = __half22float2(*reinterpret_cast<__half2*>(&w1[q]));
            float2 f2 = __half22float2(*reinterpret_cast<__half2*>(&w2[q]));
            float2 f3 = __half22float2(*reinterpret_cast<__half2*>(&w3[q]));
            acc[2 * q]     += (f0.x + f1.x) + (f2.x + f3.x);
            acc[2 * q + 1] += (f0.y + f1.y) + (f2.y + f3.y);
        }
    }
    for (; e < e1; e++) {
        int j0 = g_csrc[e];
        uint2 p0 = *reinterpret_cast<const uint2*>(yxb + ((size_t)j0 * 128 + col) * 2);
        uint32_t w0[2] = {p0.x, p0.y};
#pragma unroll
        for (int q = 0; q < 2; q++) {
            float2 f0 = __half22float2(*reinterpret_cast<__half2*>(&w0[q]));
            acc[2 * q] += f0.x;
            acc[2 * q + 1] += f0.y;
        }
    }
    float dv = g_dinv[node];
    float4 y = *reinterpret_cast<const float4*>(yh + (size_t)node * 128 + col);
    float4 o;
    o.x = y.x - dv * acc[0];
    o.y = y.y - dv * acc[1];
    o.z = y.z - dv * acc[2];
    o.w = y.w - dv * acc[3];
    *reinterpret_cast<float4*>(out + (size_t)node * 128 + col) = o;
}

// ---------------- launch -----------------------------------------------------
static inline uint32_t mk_idesc(int N) {
    return (1u << 4) | ((uint32_t)(N / 8) << 17) | (8u << 24);
}

extern "C" void kernel_launch(void* const* d_in, const int* in_sizes, int n_in,
                              void* d_out, int out_size) {
    const float* x   = (const float*)d_in[0];
    const int*   src = (const int*)d_in[1];
    const int*   dst = (const int*)d_in[2];
    const float* W1  = (const float*)d_in[3];
    const float* b1  = (const float*)d_in[4];
    const float* W2  = (const float*)d_in[5];
    const float* b2  = (const float*)d_in[6];
    const float* W3  = (const float*)d_in[7];
    const float* b3  = (const float*)d_in[8];
    float* out = (float*)d_out;

    void* p;
    cudaGetSymbolAddress(&p, g_yh);   float*  yhf = (float*)p;
    __half* yhh = (__half*)yhf;
    cudaGetSymbolAddress(&p, g_yxA);  __half* yxA = (__half*)p;
    cudaGetSymbolAddress(&p, g_yxB);  __half* yxB = (__half*)p;
    cudaGetSymbolAddress(&p, g_Whi);  __half* Whi = (__half*)p;
    cudaGetSymbolAddress(&p, g_Wlo);  __half* Wlo = (__half*)p;
    void* degp; cudaGetSymbolAddress(&degp, g_deg);

    size_t shm = 197632;  // 64KB A + 2x64KB B + align pad
    cudaFuncSetAttribute(k_fused<0>, cudaFuncAttributeMaxDynamicSharedMemorySize, shm);
    cudaFuncSetAttribute(k_fused<1>, cudaFuncAttributeMaxDynamicSharedMemorySize, shm);

    static cudaStream_t s2 = nullptr;
    static cudaEvent_t evFork = nullptr, evJoin = nullptr;
    if (!s2) {
        cudaStreamCreateWithFlags(&s2, cudaStreamNonBlocking);
        cudaEventCreateWithFlags(&evFork, cudaEventDisableTiming);
        cudaEventCreateWithFlags(&evJoin, cudaEventDisableTiming);
    }

    // ---- fork: CSR build on stream 0  ||  weight conversion on s2 ----
    cudaEventRecord(evFork, 0);
    cudaStreamWaitEvent(s2, evFork, 0);

    int nblk = (MTOT + 1023) / 1024;  // 49
    cudaMemsetAsync(degp, 0, MTOT * sizeof(int), 0);
    k_count<<<(NE + 255) / 256, 256>>>(dst);
    k_scan1<<<nblk, 1024>>>();
    k_scan2<<<1, 64>>>(nblk);
    k_scan3<<<nblk, 1024>>>();
    k_scatter<<<(NE + 255) / 256, 256>>>(src, dst);

    k_convW2<<<(256 * 256 + 255) / 256, 256, 0, s2>>>(W1, 128, 256, Whi, Wlo);
    k_convW2<<<(512 * 256 + 255) / 256, 256, 0, s2>>>(W2, 256, 256, Whi + 65536, Wlo + 65536);
    k_convW2<<<(512 * 128 + 255) / 256, 256, 0, s2>>>(W3, 256, 128, Whi + 196608, Wlo + 196608);

    cudaEventRecord(evJoin, s2);
    cudaStreamWaitEvent(0, evJoin, 0);
    // ---- join ----

    uint32_t id256 = mk_idesc(256), id128 = mk_idesc(128);
    int gg = (MTOT + 127) / 128;  // 391
    int gs = (MTOT + 7) / 8;      // 6250

    // L1: A from x; K=128
    k_fused<0><<<gg, 256, shm>>>(x, nullptr, nullptr, 128, Whi, Wlo, b1, 256, id256,
                                 yhh, nullptr, yxA);
    // L2-4: A = tanh(yh - dv*Σ yx); K=256; yx ping-pong
    k_fused<1><<<gg, 256, shm>>>(nullptr, yxA, yhh, 256, Whi + 65536, Wlo + 65536, b2,
                                 256, id256, yhh, nullptr, yxB);
    k_fused<1><<<gg, 256, shm>>>(nullptr, yxB, yhh, 256, Whi + 65536, Wlo + 65536, b2,
                                 256, id256, yhh, nullptr, yxA);
    k_fused<1><<<gg, 256, shm>>>(nullptr, yxA, yhh, 256, Whi + 65536, Wlo + 65536, b2,
                                 256, id256, yhh, nullptr, yxB);
    // L5: K=256, Nout=128; fp32 yh
    k_fused<1><<<gg, 256, shm>>>(nullptr, yxB, yhh, 256, Whi + 196608, Wlo + 196608, b3,
                                 128, id128, nullptr, yhf, yxA);
    // final: out = yh - dv*Σ yx (fp32, no tanh)
    k_aggF<<<gs, 256>>>(yhf, yxA, out);
}

// round 10
// speedup vs baseline: 2.2510x; 2.2510x over previous
#include <cuda_runtime.h>
#include <cuda_bf16.h>
#include <cuda_fp16.h>
#include <stdint.h>
#include <math.h>

#define MTOT 50000
#define NE   800000

#if defined(__CUDA_ARCH_FEAT_SM103_ALL) || defined(__CUDA_ARCH_FEAT_SM100_ALL) || \
    defined(__CUDA_ARCH_FEAT_SM101_ALL) || defined(__CUDA_ARCH_FEAT_SM110_ALL)
#define TC_OK 1
#else
#define TC_OK 0
#endif

// ---------------- device scratch (no cudaMalloc) ----------------------------
__device__ __align__(16) __half g_act[(size_t)MTOT * 256];
__device__ __align__(16) float  g_yh[(size_t)MTOT * 256];   // fp32 L5; fp16 view L1-4
__device__ __align__(16) __half g_yx[(size_t)MTOT * 256];
__device__ __align__(16) __half g_Whi[262144];
__device__ __align__(16) __half g_Wlo[262144];
__device__ float g_dinv[MTOT];
__device__ int   g_deg[MTOT];
__device__ int   g_off[MTOT + 1];
__device__ int   g_cur[MTOT];
__device__ int   g_csrc[NE];
__device__ int   g_bsum[64];

// ---------------- small helpers ---------------------------------------------
__device__ __forceinline__ uint32_t smem_u32(const void* p) {
    uint32_t a;
    asm("{ .reg .u64 t; cvta.to.shared.u64 t, %1; cvt.u32.u64 %0, t; }" : "=r"(a) : "l"(p));
    return a;
}
__device__ __forceinline__ bool elect1() {
    uint32_t p;
    asm volatile("{\n\t.reg .pred p;\n\telect.sync _|p, 0xFFFFFFFF;\n\tselp.b32 %0,1,0,p;\n\t}" : "=r"(p));
    return p != 0;
}
__device__ __forceinline__ void mbar_init(uint32_t mbar, uint32_t cnt) {
    asm volatile("mbarrier.init.shared.b64 [%0], %1;" :: "r"(mbar), "r"(cnt) : "memory");
}
__device__ __forceinline__ void mbar_wait(uint32_t mbar, uint32_t parity) {
    uint32_t done;
    asm volatile("{\n\t.reg .pred p;\n\tmbarrier.try_wait.parity.acquire.cta.shared::cta.b64 p, [%1], %2;\n\tselp.b32 %0,1,0,p;\n\t}"
                 : "=r"(done) : "r"(mbar), "r"(parity) : "memory");
    if (!done) {
        asm volatile("{\n\t.reg .pred P1;\nWL_%=:\n\tmbarrier.try_wait.parity.acquire.cta.shared::cta.b64 P1, [%0], %1, 0x989680;\n\t@P1 bra.uni WD_%=;\n\tbra.uni WL_%=;\nWD_%=:\n\t}"
                     :: "r"(mbar), "r"(parity) : "memory");
    }
}
__device__ __forceinline__ float tanha(float x) {
    float y; asm("tanh.approx.f32 %0, %1;" : "=f"(y) : "f"(x)); return y;
}
__device__ __forceinline__ uint32_t pkh2(float a, float b) {
    __half2 h = __floats2half2_rn(a, b);
    return *reinterpret_cast<uint32_t*>(&h);
}
#define CPA16(sm_u32, gptr) \
    asm volatile("cp.async.cg.shared.global [%0], [%1], 16;" :: "r"(sm_u32), "l"(gptr) : "memory")
#define CPA_COMMIT() asm volatile("cp.async.commit_group;" ::: "memory")
#define CPA_WAIT0()  asm volatile("cp.async.wait_group 0;" ::: "memory")

#if TC_OK
__device__ __forceinline__ uint64_t mk_desc(uint32_t addr) {
    // SW128, version=1(Blackwell), SBO=64, LBO=1, start=addr>>4
    return 0x4000404000010000ULL | ((uint64_t)(addr >> 4) & 0x3FFF);
}
__device__ __forceinline__ void mma_ss_f16(uint32_t d, uint64_t ad, uint64_t bd,
                                           uint32_t idesc, uint32_t en) {
    asm volatile("{\n\t.reg .pred p;\n\tsetp.ne.u32 p, %4, 0;\n\t"
                 "tcgen05.mma.cta_group::1.kind::f16 [%0], %1, %2, %3, {%5,%5,%5,%5}, p;\n\t}"
                 :: "r"(d), "l"(ad), "l"(bd), "r"(idesc), "r"(en), "r"(0u) : "memory");
}
#define LDTM32(r, addr) \
    asm volatile("tcgen05.ld.sync.aligned.32x32b.x32.b32 " \
        "{%0,%1,%2,%3,%4,%5,%6,%7,%8,%9,%10,%11,%12,%13,%14,%15," \
        "%16,%17,%18,%19,%20,%21,%22,%23,%24,%25,%26,%27,%28,%29,%30,%31}, [%32];" \
        : "=r"((r)[0]),"=r"((r)[1]),"=r"((r)[2]),"=r"((r)[3]),"=r"((r)[4]),"=r"((r)[5]),"=r"((r)[6]),"=r"((r)[7]), \
          "=r"((r)[8]),"=r"((r)[9]),"=r"((r)[10]),"=r"((r)[11]),"=r"((r)[12]),"=r"((r)[13]),"=r"((r)[14]),"=r"((r)[15]), \
          "=r"((r)[16]),"=r"((r)[17]),"=r"((r)[18]),"=r"((r)[19]),"=r"((r)[20]),"=r"((r)[21]),"=r"((r)[22]),"=r"((r)[23]), \
          "=r"((r)[24]),"=r"((r)[25]),"=r"((r)[26]),"=r"((r)[27]),"=r"((r)[28]),"=r"((r)[29]),"=r"((r)[30]),"=r"((r)[31]) \
        : "r"(addr))
#endif

// ---------------- CSR build (parallel scan) ----------------------------------
__global__ void k_count(const int* __restrict__ dst) {
    int e = blockIdx.x * blockDim.x + threadIdx.x;
    if (e < NE) atomicAdd(&g_deg[dst[e]], 1);
}
__global__ void k_scan1() {
    __shared__ int sh[1024];
    int t = threadIdx.x;
    int i = blockIdx.x * 1024 + t;
    int v = (i < MTOT) ? g_deg[i] : 0;
    sh[t] = v;
    __syncthreads();
    for (int ofs = 1; ofs < 1024; ofs <<= 1) {
        int x = (t >= ofs) ? sh[t - ofs] : 0;
        __syncthreads();
        sh[t] += x;
        __syncthreads();
    }
    if (i < MTOT) g_off[i] = sh[t] - v;
    if (t == 1023) g_bsum[blockIdx.x] = sh[1023];
}
__global__ void k_scan2(int nblk) {
    __shared__ int sh[64];
    int t = threadIdx.x;
    int v = (t < nblk) ? g_bsum[t] : 0;
    sh[t] = v;
    __syncthreads();
    for (int ofs = 1; ofs < 64; ofs <<= 1) {
        int x = (t >= ofs) ? sh[t - ofs] : 0;
        __syncthreads();
        sh[t] += x;
        __syncthreads();
    }
    if (t < nblk) g_bsum[t] = sh[t] - v;
}
__global__ void k_scan3() {
    int i = blockIdx.x * 1024 + threadIdx.x;
    if (i < MTOT) {
        int o = g_off[i] + g_bsum[i >> 10];
        g_off[i] = o;
        g_cur[i] = o;
        int d = g_deg[i];
        g_dinv[i] = (d > 0) ? rsqrtf((float)d) : 0.0f;
    }
    if (i == 0) g_off[MTOT] = NE;
}
__global__ void k_scatter(const int* __restrict__ src, const int* __restrict__ dst) {
    int e = blockIdx.x * blockDim.x + threadIdx.x;
    if (e < NE) {
        int p = atomicAdd(&g_cur[dst[e]], 1);
        g_csrc[p] = src[e];
    }
}

// ---------------- converters ------------------------------------------------
__global__ void k_convW2(const float* __restrict__ W, int F, int N,
                         __half* __restrict__ oh, __half* __restrict__ ol) {
    int idx = blockIdx.x * blockDim.x + threadIdx.x;
    if (idx >= 2 * F * N) return;
    int k2 = idx / N, n = idx % N;
    int half = (k2 >= F);
    int k = k2 - half * F;
    float v = W[(size_t)k2 * N + n];
    __half h = __float2half_rn(v);
    size_t o = (size_t)half * N * F + (size_t)n * F + k;
    oh[o] = h;
    ol[o] = __float2half_rn(v - __half2float(h));
}

__global__ void k_convX(const float* __restrict__ x, __half* __restrict__ act) {
    int idx = blockIdx.x * blockDim.x + threadIdx.x;
    if (idx >= MTOT * 32) return;
    int m = idx >> 5, c4 = (idx & 31) << 2;
    float4 v = *reinterpret_cast<const float4*>(x + (size_t)m * 128 + c4);
    uint2 p;
    p.x = pkh2(v.x, v.y);
    p.y = pkh2(v.z, v.w);
    *reinterpret_cast<uint2*>((char*)act + ((size_t)m * 128 + c4) * 2) = p;
}

// ---------------- aggregation + activation ----------------------------------
template <int CPL, int ACT, int YH16>
__global__ void k_aggact(const void* __restrict__ yhp, const __half* __restrict__ yx,
                         int Nout, __half* __restrict__ oact, float* __restrict__ of32) {
    int node = blockIdx.x * 8 + (threadIdx.x >> 5);
    if (node >= MTOT) return;
    int lane = threadIdx.x & 31;
    int col = lane * CPL;
    float acc[CPL];
#pragma unroll
    for (int i = 0; i < CPL; i++) acc[i] = 0.f;
    int e0 = g_off[node], e1 = g_off[node + 1];
    const char* yxb = (const char*)yx;
    int e = e0;

    if constexpr (CPL == 8) {
        for (; e + 4 <= e1; e += 4) {
            int j0 = g_csrc[e], j1 = g_csrc[e + 1], j2 = g_csrc[e + 2], j3 = g_csrc[e + 3];
            uint4 p0 = *reinterpret_cast<const uint4*>(yxb + ((size_t)j0 * Nout + col) * 2);
            uint4 p1 = *reinterpret_cast<const uint4*>(yxb + ((size_t)j1 * Nout + col) * 2);
            uint4 p2 = *reinterpret_cast<const uint4*>(yxb + ((size_t)j2 * Nout + col) * 2);
            uint4 p3 = *reinterpret_cast<const uint4*>(yxb + ((size_t)j3 * Nout + col) * 2);
            uint32_t w0[4] = {p0.x, p0.y, p0.z, p0.w};
            uint32_t w1[4] = {p1.x, p1.y, p1.z, p1.w};
            uint32_t w2[4] = {p2.x, p2.y, p2.z, p2.w};
            uint32_t w3[4] = {p3.x, p3.y, p3.z, p3.w};
#pragma unroll
            for (int q = 0; q < 4; q++) {
                float2 f0 = __half22float2(*reinterpret_cast<__half2*>(&w0[q]));
                float2 f1 = __half22float2(*reinterpret_cast<__half2*>(&w1[q]));
                float2 f2 = __half22float2(*reinterpret_cast<__half2*>(&w2[q]));
                float2 f3 = __half22float2(*reinterpret_cast<__half2*>(&w3[q]));
                acc[2 * q]     += (f0.x + f1.x) + (f2.x + f3.x);
                acc[2 * q + 1] += (f0.y + f1.y) + (f2.y + f3.y);
            }
        }
        for (; e < e1; e++) {
            int j0 = g_csrc[e];
            uint4 p0 = *reinterpret_cast<const uint4*>(yxb + ((size_t)j0 * Nout + col) * 2);
            uint32_t w0[4] = {p0.x, p0.y, p0.z, p0.w};
#pragma unroll
            for (int q = 0; q < 4; q++) {
                float2 f0 = __half22float2(*reinterpret_cast<__half2*>(&w0[q]));
                acc[2 * q] += f0.x; acc[2 * q + 1] += f0.y;
            }
        }
    } else {
        for (; e + 4 <= e1; e += 4) {
            int j0 = g_csrc[e], j1 = g_csrc[e + 1], j2 = g_csrc[e + 2], j3 = g_csrc[e + 3];
            uint2 p0 = *reinterpret_cast<const uint2*>(yxb + ((size_t)j0 * Nout + col) * 2);
            uint2 p1 = *reinterpret_cast<const uint2*>(yxb + ((size_t)j1 * Nout + col) * 2);
            uint2 p2 = *reinterpret_cast<const uint2*>(yxb + ((size_t)j2 * Nout + col) * 2);
            uint2 p3 = *reinterpret_cast<const uint2*>(yxb + ((size_t)j3 * Nout + col) * 2);
            uint32_t w0[2] = {p0.x, p0.y};
            uint32_t w1[2] = {p1.x, p1.y};
            uint32_t w2[2] = {p2.x, p2.y};
            uint32_t w3[2] = {p3.x, p3.y};
#pragma unroll
            for (int q = 0; q < 2; q++) {
                float2 f0 = __half22float2(*reinterpret_cast<__half2*>(&w0[q]));
                float2 f1 = __half22float2(*reinterpret_cast<__half2*>(&w1[q]));
                float2 f2 = __half22float2(*reinterpret_cast<__half2*>(&w2[q]));
                float2 f3 = __half22float2(*reinterpret_cast<__half2*>(&w3[q]));
                acc[2 * q]     += (f0.x + f1.x) + (f2.x + f3.x);
                acc[2 * q + 1] += (f0.y + f1.y) + (f2.y + f3.y);
            }
        }
        for (; e < e1; e++) {
            int j0 = g_csrc[e];
            uint2 p0 = *reinterpret_cast<const uint2*>(yxb + ((size_t)j0 * Nout + col) * 2);
            uint32_t w0[2] = {p0.x, p0.y};
#pragma unroll
            for (int q = 0; q < 2; q++) {
                float2 f0 = __half22float2(*reinterpret_cast<__half2*>(&w0[q]));
                acc[2 * q] += f0.x; acc[2 * q + 1] += f0.y;
            }
        }
    }

    float dv = g_dinv[node];
    float v[CPL];
    if constexpr (YH16) {
        const char* yhb = (const char*)yhp;
        if constexpr (CPL == 8) {
            uint4 y = *reinterpret_cast<const uint4*>(yhb + ((size_t)node * Nout + col) * 2);
            uint32_t yw[4] = {y.x, y.y, y.z, y.w};
#pragma unroll
            for (int q = 0; q < 4; q++) {
                float2 f = __half22float2(*reinterpret_cast<__half2*>(&yw[q]));
                v[2 * q]     = f.x - dv * acc[2 * q];
                v[2 * q + 1] = f.y - dv * acc[2 * q + 1];
            }
        } else {
            uint2 y = *reinterpret_cast<const uint2*>(yhb + ((size_t)node * Nout + col) * 2);
            uint32_t yw[2] = {y.x, y.y};
#pragma unroll
            for (int q = 0; q < 2; q++) {
                float2 f = __half22float2(*reinterpret_cast<__half2*>(&yw[q]));
                v[2 * q]     = f.x - dv * acc[2 * q];
                v[2 * q + 1] = f.y - dv * acc[2 * q + 1];
            }
        }
    } else {
        const float* yh = (const float*)yhp;
#pragma unroll
        for (int i = 0; i < CPL; i += 4) {
            float4 y = *reinterpret_cast<const float4*>(yh + (size_t)node * Nout + col + i);
            v[i + 0] = y.x - dv * acc[i + 0];
            v[i + 1] = y.y - dv * acc[i + 1];
            v[i + 2] = y.z - dv * acc[i + 2];
            v[i + 3] = y.w - dv * acc[i + 3];
        }
    }
    if constexpr (ACT) {
#pragma unroll
        for (int i = 0; i < CPL; i++) v[i] = tanha(v[i]);
        size_t wo = ((size_t)node * Nout + col) * 2;
        if constexpr (CPL == 8) {
            uint4 p;
            p.x = pkh2(v[0], v[1]); p.y = pkh2(v[2], v[3]);
            p.z = pkh2(v[4], v[5]); p.w = pkh2(v[6], v[7]);
            *reinterpret_cast<uint4*>((char*)oact + wo) = p;
        } else {
            uint2 p;
            p.x = pkh2(v[0], v[1]); p.y = pkh2(v[2], v[3]);
            *reinterpret_cast<uint2*>((char*)oact + wo) = p;
        }
    } else {
#pragma unroll
        for (int i = 0; i < CPL; i += 4) {
            float4 o = make_float4(v[i], v[i + 1], v[i + 2], v[i + 3]);
            *reinterpret_cast<float4*>(of32 + (size_t)node * Nout + col + i) = o;
        }
    }
}

// ---------------- tcgen05 dual-output fp16 GEMM ------------------------------
// One CTA = 128 rows; yh = act@Wh + b (TMEM [0,256)), yx = dinv*(act@Wx) ([256,512)).
// 3-stage B pipeline with cp.async fills; A slots 2x16KB @0/@16K; B @32K+(s%3)*64K.
__global__ void __launch_bounds__(256, 1) k_gemm_tc(
    const __half* __restrict__ act, int K,
    const __half* __restrict__ Whi, const __half* __restrict__ Wlo,
    const float* __restrict__ bias, int Nout, uint32_t idesc,
    float* __restrict__ yhf32, __half* __restrict__ yh16, __half* __restrict__ yx)
{
#if TC_OK
    extern __shared__ char smraw[];
    __shared__ __align__(16) uint32_t ctrl[8];  // [0]=tmem ptr; mbars at +8,+16,+24
    int tid = threadIdx.x, wid = tid >> 5;
    uint32_t cu = smem_u32(ctrl);

    if (wid == 0) {
        asm volatile("tcgen05.alloc.cta_group::1.sync.aligned.shared::cta.b32 [%0], %1;"
                     :: "r"(cu), "r"(512u) : "memory");
        asm volatile("tcgen05.relinquish_alloc_permit.cta_group::1.sync.aligned;");
    }
    if (tid == 0) { mbar_init(cu + 8, 1); mbar_init(cu + 16, 1); mbar_init(cu + 24, 1); }
    __syncthreads();
    uint32_t tmem;
    asm("ld.shared.b32 %0, [%1];" : "=r"(tmem) : "r"(cu));

    uint32_t raw = smem_u32(smraw);
    uint32_t sb = (raw + 1023) & ~1023u;
    char* sm = smraw + (sb - raw);

    int m0 = blockIdx.x * 128;
    const char* Ab = (const char*)act;
    int NS = (K >> 6) * 2;
    int nbB = Nout << 3;
    int loOfs = Nout << 7;

    for (int s = 0; s < NS; s++) {
        int kc = s >> 1, out = s & 1, buf = s % 3;
        uint32_t bstu = sb + 32768 + buf * 65536;
        if (s >= 3) {
            int idx = (s - 3 - buf) / 3;
            mbar_wait(cu + 8 + buf * 8, idx & 1);
        }

        if (out == 0) {
            uint32_t astu = sb + (kc & 1) * 16384;
            char* ast = sm + (kc & 1) * 16384;
            for (int i = tid; i < 1024; i += 256) {
                int row = i >> 3, c = i & 7;
                int m = m0 + row;
                uint32_t bo = (row << 7) + (c << 4);
                uint32_t so = bo ^ ((bo >> 3) & 0x70);
                if (m < MTOT) {
                    CPA16(astu + so, Ab + ((size_t)m * K + (kc << 6) + (c << 3)) * 2);
                } else {
                    *reinterpret_cast<uint4*>(ast + so) = make_uint4(0, 0, 0, 0);
                }
            }
        }
        {
            size_t wofs = (size_t)out * Nout * K;
            const char* Bh = (const char*)(Whi + wofs);
            const char* Bl = (const char*)(Wlo + wofs);
            for (int i = tid; i < nbB; i += 256) {
                int n = i >> 3, c = i & 7;
                size_t go = ((size_t)n * K + (kc << 6) + (c << 3)) * 2;
                uint32_t bo = (n << 7) + (c << 4);
                uint32_t so = bo ^ ((bo >> 3) & 0x70);
                CPA16(bstu + so, Bh + go);
                CPA16(bstu + loOfs + so, Bl + go);
            }
        }
        CPA_COMMIT();
        CPA_WAIT0();
        asm volatile("fence.proxy.async.shared::cta;" ::: "memory");
        __syncthreads();

        if (wid == 0 && elect1()) {
            uint64_t dA  = mk_desc(sb + (kc & 1) * 16384);
            uint64_t dBh = mk_desc(bstu);
            uint64_t dBl = mk_desc(bstu + loOfs);
            uint32_t D = tmem + out * 256;
#pragma unroll
            for (int k = 0; k < 4; k++) {
                uint64_t o = (uint64_t)(k * 2);
                mma_ss_f16(D, dA + o, dBh + o, idesc, (uint32_t)((kc | k) != 0));
                mma_ss_f16(D, dA + o, dBl + o, idesc, 1u);
            }
            asm volatile("tcgen05.commit.cta_group::1.mbarrier::arrive::one.shared::cluster.b64 [%0];"
                         :: "r"(cu + 8 + buf * 8) : "memory");
        }
    }

    for (int s = (NS >= 3 ? NS - 3 : 0); s < NS; s++) {
        int b = s % 3;
        int idx = (s - b) / 3;
        mbar_wait(cu + 8 + b * 8, idx & 1);
    }
    asm volatile("tcgen05.fence::after_thread_sync;" ::: "memory");

    int lane = tid & 31, sub = wid & 3, wg = wid >> 2;
    int m = m0 + sub * 32 + lane;
    int niter = Nout >> 5;
    uint32_t base = tmem + wg * 256;
    for (int cc = 0; cc < niter; cc++) {
        uint32_t r[32];
        LDTM32(r, base + cc * 32);
        asm volatile("tcgen05.wait::ld.sync.aligned;" ::: "memory");
        if (m < MTOT) {
            int nb = cc * 32;
            if (wg == 0) {
                if (yh16) {
                    uint32_t hp[16];
#pragma unroll
                    for (int q = 0; q < 16; q++)
                        hp[q] = pkh2(__uint_as_float(r[2 * q])     + bias[nb + 2 * q],
                                     __uint_as_float(r[2 * q + 1]) + bias[nb + 2 * q + 1]);
                    uint4* dp = reinterpret_cast<uint4*>((char*)yh16 + ((size_t)m * Nout + nb) * 2);
#pragma unroll
                    for (int q = 0; q < 4; q++)
                        dp[q] = make_uint4(hp[4 * q], hp[4 * q + 1], hp[4 * q + 2], hp[4 * q + 3]);
                } else {
                    float4* dp = reinterpret_cast<float4*>(yhf32 + (size_t)m * Nout + nb);
#pragma unroll
                    for (int q = 0; q < 8; q++) {
                        float4 v;
                        v.x = __uint_as_float(r[q * 4 + 0]) + bias[nb + q * 4 + 0];
                        v.y = __uint_as_float(r[q * 4 + 1]) + bias[nb + q * 4 + 1];
                        v.z = __uint_as_float(r[q * 4 + 2]) + bias[nb + q * 4 + 2];
                        v.w = __uint_as_float(r[q * 4 + 3]) + bias[nb + q * 4 + 3];
                        dp[q] = v;
                    }
                }
            } else {
                float dv = g_dinv[m];
                uint32_t hp[16];
#pragma unroll
                for (int q = 0; q < 16; q++)
                    hp[q] = pkh2(dv * __uint_as_float(r[2 * q]),
                                 dv * __uint_as_float(r[2 * q + 1]));
                uint4* dp = reinterpret_cast<uint4*>((char*)yx + ((size_t)m * Nout + nb) * 2);
#pragma unroll
                for (int q = 0; q < 4; q++)
                    dp[q] = make_uint4(hp[4 * q], hp[4 * q + 1], hp[4 * q + 2], hp[4 * q + 3]);
            }
        }
    }
    __syncthreads();
    if (wid == 0) {
        asm volatile("tcgen05.dealloc.cta_group::1.sync.aligned.b32 %0, %1;"
                     :: "r"(tmem), "r"(512u));
    }
#endif  // TC_OK
}

// ---------------- SIMT fallback GEMM (non-"a" passes only) -------------------
__global__ void __launch_bounds__(256) k_gemm_fb(
    const __half* __restrict__ act, int K,
    const __half* __restrict__ Whi, const __half* __restrict__ Wlo,
    const float* __restrict__ bias, int Nout, uint32_t idesc,
    float* __restrict__ yhf32, __half* __restrict__ yh16, __half* __restrict__ yx)
{
#if !TC_OK
    __shared__ float As[16][132];
    __shared__ float Bs[16][128];
    int tid = threadIdx.x;
    int tx = tid & 15, ty = tid >> 4;
    int m0 = blockIdx.x * 128;
    size_t hofs = (size_t)blockIdx.y * Nout * K;
    const __half* Bh = Whi + hofs;
    const __half* Bl = Wlo + hofs;

    for (int n0 = 0; n0 < Nout; n0 += 128) {
        float acc[8][8];
#pragma unroll
        for (int i = 0; i < 8; i++)
#pragma unroll
            for (int j = 0; j < 8; j++) acc[i][j] = 0.f;

        for (int k0 = 0; k0 < K; k0 += 16) {
            for (int i = tid; i < 2048; i += 256) {
                int r = i >> 4, k = i & 15;
                int m = m0 + r;
                As[k][r] = (m < MTOT) ? __half2float(act[(size_t)m * K + k0 + k]) : 0.f;
            }
            for (int i = tid; i < 2048; i += 256) {
                int r = i >> 4, k = i & 15;
                size_t o = (size_t)(n0 + r) * K + k0 + k;
                Bs[k][r] = __half2float(Bh[o]) + __half2float(Bl[o]);
            }
            __syncthreads();
#pragma unroll
            for (int k = 0; k < 16; k++) {
                float a[8], b[8];
#pragma unroll
                for (int i = 0; i < 8; i++) a[i] = As[k][ty * 8 + i];
#pragma unroll
                for (int j = 0; j < 8; j++) b[j] = Bs[k][tx * 8 + j];
#pragma unroll
                for (int i = 0; i < 8; i++)
#pragma unroll
                    for (int j = 0; j < 8; j++) acc[i][j] += a[i] * b[j];
            }
            __syncthreads();
        }

#pragma unroll
        for (int i = 0; i < 8; i++) {
            int m = m0 + ty * 8 + i;
            if (m >= MTOT) continue;
            float dv = g_dinv[m];
#pragma unroll
            for (int j = 0; j < 8; j++) {
                int n = n0 + tx * 8 + j;
                if (blockIdx.y == 0) {
                    float v = acc[i][j] + bias[n];
                    if (yh16) yh16[(size_t)m * Nout + n] = __float2half_rn(v);
                    else      yhf32[(size_t)m * Nout + n] = v;
                } else {
                    yx[(size_t)m * Nout + n] = __float2half_rn(dv * acc[i][j]);
                }
            }
        }
        __syncthreads();
    }
#endif  // !TC_OK
}

// ---------------- launch -----------------------------------------------------
static inline uint32_t mk_idesc(int N) {
    return (1u << 4) | ((uint32_t)(N / 8) << 17) | (8u << 24);
}

extern "C" void kernel_launch(void* const* d_in, const int* in_sizes, int n_in,
                              void* d_out, int out_size) {
    const float* x   = (const float*)d_in[0];
    const int*   src = (const int*)d_in[1];
    const int*   dst = (const int*)d_in[2];
    const float* W1  = (const float*)d_in[3];
    const float* b1  = (const float*)d_in[4];
    const float* W2  = (const float*)d_in[5];
    const float* b2  = (const float*)d_in[6];
    const float* W3  = (const float*)d_in[7];
    const float* b3  = (const float*)d_in[8];
    float* out = (float*)d_out;

    void* p;
    cudaGetSymbolAddress(&p, g_act);  __half* act  = (__half*)p;
    cudaGetSymbolAddress(&p, g_yh);   float*  yhf  = (float*)p;
    __half* yhh = (__half*)yhf;
    cudaGetSymbolAddress(&p, g_yx);   __half* yx   = (__half*)p;
    cudaGetSymbolAddress(&p, g_Whi);  __half* Whi  = (__half*)p;
    cudaGetSymbolAddress(&p, g_Wlo);  __half* Wlo  = (__half*)p;
    void* degp; cudaGetSymbolAddress(&degp, g_deg);

    cudaFuncSetAttribute(k_gemm_tc, cudaFuncAttributeMaxDynamicSharedMemorySize, 231424);

    static cudaStream_t s2 = nullptr;
    static cudaEvent_t evFork = nullptr, evJoin = nullptr;
    if (!s2) {
        cudaStreamCreateWithFlags(&s2, cudaStreamNonBlocking);
        cudaEventCreateWithFlags(&evFork, cudaEventDisableTiming);
        cudaEventCreateWithFlags(&evJoin, cudaEventDisableTiming);
    }

    // ---- fork: CSR build on stream 0  ||  conversions on s2 ----
    cudaEventRecord(evFork, 0);
    cudaStreamWaitEvent(s2, evFork, 0);

    int nblk = (MTOT + 1023) / 1024;  // 49
    cudaMemsetAsync(degp, 0, MTOT * sizeof(int), 0);
    k_count<<<(NE + 255) / 256, 256>>>(dst);
    k_scan1<<<nblk, 1024>>>();
    k_scan2<<<1, 64>>>(nblk);
    k_scan3<<<nblk, 1024>>>();
    k_scatter<<<(NE + 255) / 256, 256>>>(src, dst);

    k_convW2<<<(256 * 256 + 255) / 256, 256, 0, s2>>>(W1, 128, 256, Whi, Wlo);
    k_convW2<<<(512 * 256 + 255) / 256, 256, 0, s2>>>(W2, 256, 256, Whi + 65536, Wlo + 65536);
    k_convW2<<<(512 * 128 + 255) / 256, 256, 0, s2>>>(W3, 256, 128, Whi + 196608, Wlo + 196608);
    k_convX<<<(MTOT * 32 + 255) / 256, 256, 0, s2>>>(x, act);

    cudaEventRecord(evJoin, s2);
    cudaStreamWaitEvent(0, evJoin, 0);
    // ---- join ----

    uint32_t id256 = mk_idesc(256), id128 = mk_idesc(128);
    int gg = (MTOT + 127) / 128;     // 391
    dim3 ggfb(gg, 2);
    int gs = (MTOT + 7) / 8;         // 6250
    size_t shm = 231424;

    auto gemm = [&](int K, const __half* bh, const __half* bl,
                    const float* bias, int Nout, uint32_t idesc, __half* y16) {
        k_gemm_tc<<<gg, 256, shm>>>(act, K, bh, bl, bias, Nout, idesc,
                                    y16 ? nullptr : yhf, y16, yx);
        k_gemm_fb<<<ggfb, 256>>>(act, K, bh, bl, bias, Nout, idesc,
                                 y16 ? nullptr : yhf, y16, yx);
    };

    // L1: K=128, Nout=256, fp16 yh
    gemm(128, Whi, Wlo, b1, 256, id256, yhh);
    k_aggact<8, 1, 1><<<gs, 256>>>(yhh, yx, 256, act, nullptr);
    // L2-4: K=256, Nout=256 (shared W2), fp16 yh
    for (int l = 0; l < 3; l++) {
        gemm(256, Whi + 65536, Wlo + 65536, b2, 256, id256, yhh);
        k_aggact<8, 1, 1><<<gs, 256>>>(yhh, yx, 256, act, nullptr);
    }
    // L5: K=256, Nout=128; fp32 yh, final out, no tanh
    gemm(256, Whi + 196608, Wlo + 196608, b3, 128, id128, nullptr);
    k_aggact<4, 0, 0><<<gs, 256>>>(yhf, yx, 128, nullptr, out);
}

// round 12
// speedup vs baseline: 2.3057x; 1.0243x over previous
#include <cuda_runtime.h>
#include <cuda_bf16.h>
#include <cuda_fp16.h>
#include <stdint.h>
#include <math.h>

#define MTOT 50000
#define NE   800000

#if defined(__CUDA_ARCH_FEAT_SM103_ALL) || defined(__CUDA_ARCH_FEAT_SM100_ALL) || \
    defined(__CUDA_ARCH_FEAT_SM101_ALL) || defined(__CUDA_ARCH_FEAT_SM110_ALL)
#define TC_OK 1
#else
#define TC_OK 0
#endif

// ---------------- device scratch (no cudaMalloc) ----------------------------
__device__ __align__(16) __half g_act[(size_t)MTOT * 256];
__device__ __align__(16) float  g_yh[(size_t)MTOT * 256];   // fp32 L5; fp16 view L1-4
__device__ __align__(16) __half g_yx[(size_t)MTOT * 256];
__device__ __align__(16) __half g_Whi[262144];
__device__ __align__(16) __half g_Wlo[262144];
__device__ float g_dinv[MTOT];
__device__ int   g_deg[MTOT];
__device__ int   g_off[MTOT + 1];
__device__ int   g_cur[MTOT];
__device__ int   g_csrc[NE];
__device__ int   g_bsum[64];

// ---------------- small helpers ---------------------------------------------
__device__ __forceinline__ uint32_t smem_u32(const void* p) {
    uint32_t a;
    asm("{ .reg .u64 t; cvta.to.shared.u64 t, %1; cvt.u32.u64 %0, t; }" : "=r"(a) : "l"(p));
    return a;
}
__device__ __forceinline__ bool elect1() {
    uint32_t p;
    asm volatile("{\n\t.reg .pred p;\n\telect.sync _|p, 0xFFFFFFFF;\n\tselp.b32 %0,1,0,p;\n\t}" : "=r"(p));
    return p != 0;
}
__device__ __forceinline__ void mbar_init(uint32_t mbar, uint32_t cnt) {
    asm volatile("mbarrier.init.shared.b64 [%0], %1;" :: "r"(mbar), "r"(cnt) : "memory");
}
__device__ __forceinline__ void mbar_wait(uint32_t mbar, uint32_t parity) {
    uint32_t done;
    asm volatile("{\n\t.reg .pred p;\n\tmbarrier.try_wait.parity.acquire.cta.shared::cta.b64 p, [%1], %2;\n\tselp.b32 %0,1,0,p;\n\t}"
                 : "=r"(done) : "r"(mbar), "r"(parity) : "memory");
    if (!done) {
        asm volatile("{\n\t.reg .pred P1;\nWL_%=:\n\tmbarrier.try_wait.parity.acquire.cta.shared::cta.b64 P1, [%0], %1, 0x989680;\n\t@P1 bra.uni WD_%=;\n\tbra.uni WL_%=;\nWD_%=:\n\t}"
                     :: "r"(mbar), "r"(parity) : "memory");
    }
}
__device__ __forceinline__ float tanha(float x) {
    float y; asm("tanh.approx.f32 %0, %1;" : "=f"(y) : "f"(x)); return y;
}
__device__ __forceinline__ uint32_t pkh2(float a, float b) {
    __half2 h = __floats2half2_rn(a, b);
    return *reinterpret_cast<uint32_t*>(&h);
}
#define CPA16(sm_u32, gptr) \
    asm volatile("cp.async.cg.shared.global [%0], [%1], 16;" :: "r"(sm_u32), "l"(gptr) : "memory")
#define CPA_COMMIT() asm volatile("cp.async.commit_group;" ::: "memory")
#define CPA_WAIT0()  asm volatile("cp.async.wait_group 0;" ::: "memory")

#if TC_OK
__device__ __forceinline__ uint64_t mk_desc(uint32_t addr) {
    // SW128, version=1(Blackwell), SBO=64, LBO=1, start=addr>>4
    return 0x4000404000010000ULL | ((uint64_t)(addr >> 4) & 0x3FFF);
}
__device__ __forceinline__ void mma_ss_f16(uint32_t d, uint64_t ad, uint64_t bd,
                                           uint32_t idesc, uint32_t en) {
    asm volatile("{\n\t.reg .pred p;\n\tsetp.ne.u32 p, %4, 0;\n\t"
                 "tcgen05.mma.cta_group::1.kind::f16 [%0], %1, %2, %3, {%5,%5,%5,%5}, p;\n\t}"
                 :: "r"(d), "l"(ad), "l"(bd), "r"(idesc), "r"(en), "r"(0u) : "memory");
}
#define LDTM32(r, addr) \
    asm volatile("tcgen05.ld.sync.aligned.32x32b.x32.b32 " \
        "{%0,%1,%2,%3,%4,%5,%6,%7,%8,%9,%10,%11,%12,%13,%14,%15," \
        "%16,%17,%18,%19,%20,%21,%22,%23,%24,%25,%26,%27,%28,%29,%30,%31}, [%32];" \
        : "=r"((r)[0]),"=r"((r)[1]),"=r"((r)[2]),"=r"((r)[3]),"=r"((r)[4]),"=r"((r)[5]),"=r"((r)[6]),"=r"((r)[7]), \
          "=r"((r)[8]),"=r"((r)[9]),"=r"((r)[10]),"=r"((r)[11]),"=r"((r)[12]),"=r"((r)[13]),"=r"((r)[14]),"=r"((r)[15]), \
          "=r"((r)[16]),"=r"((r)[17]),"=r"((r)[18]),"=r"((r)[19]),"=r"((r)[20]),"=r"((r)[21]),"=r"((r)[22]),"=r"((r)[23]), \
          "=r"((r)[24]),"=r"((r)[25]),"=r"((r)[26]),"=r"((r)[27]),"=r"((r)[28]),"=r"((r)[29]),"=r"((r)[30]),"=r"((r)[31]) \
        : "r"(addr))
#endif

// ---------------- CSR build (parallel scan) ----------------------------------
__global__ void k_count(const int* __restrict__ dst) {
    int e = blockIdx.x * blockDim.x + threadIdx.x;
    if (e < NE) atomicAdd(&g_deg[dst[e]], 1);
}
__global__ void k_scan1() {
    __shared__ int sh[1024];
    int t = threadIdx.x;
    int i = blockIdx.x * 1024 + t;
    int v = (i < MTOT) ? g_deg[i] : 0;
    sh[t] = v;
    __syncthreads();
    for (int ofs = 1; ofs < 1024; ofs <<= 1) {
        int x = (t >= ofs) ? sh[t - ofs] : 0;
        __syncthreads();
        sh[t] += x;
        __syncthreads();
    }
    if (i < MTOT) g_off[i] = sh[t] - v;
    if (t == 1023) g_bsum[blockIdx.x] = sh[1023];
}
__global__ void k_scan2(int nblk) {
    __shared__ int sh[64];
    int t = threadIdx.x;
    int v = (t < nblk) ? g_bsum[t] : 0;
    sh[t] = v;
    __syncthreads();
    for (int ofs = 1; ofs < 64; ofs <<= 1) {
        int x = (t >= ofs) ? sh[t - ofs] : 0;
        __syncthreads();
        sh[t] += x;
        __syncthreads();
    }
    if (t < nblk) g_bsum[t] = sh[t] - v;
}
__global__ void k_scan3() {
    int i = blockIdx.x * 1024 + threadIdx.x;
    if (i < MTOT) {
        int o = g_off[i] + g_bsum[i >> 10];
        g_off[i] = o;
        g_cur[i] = o;
        int d = g_deg[i];
        g_dinv[i] = (d > 0) ? rsqrtf((float)d) : 0.0f;
    }
    if (i == 0) g_off[MTOT] = NE;
}
__global__ void k_scatter(const int* __restrict__ src, const int* __restrict__ dst) {
    int e = blockIdx.x * blockDim.x + threadIdx.x;
    if (e < NE) {
        int p = atomicAdd(&g_cur[dst[e]], 1);
        g_csrc[p] = src[e];
    }
}

// ---------------- converters ------------------------------------------------
__global__ void k_convW2(const float* __restrict__ W, int F, int N,
                         __half* __restrict__ oh, __half* __restrict__ ol) {
    int idx = blockIdx.x * blockDim.x + threadIdx.x;
    if (idx >= 2 * F * N) return;
    int k2 = idx / N, n = idx % N;
    int half = (k2 >= F);
    int k = k2 - half * F;
    float v = W[(size_t)k2 * N + n];
    __half h = __float2half_rn(v);
    size_t o = (size_t)half * N * F + (size_t)n * F + k;
    oh[o] = h;
    ol[o] = __float2half_rn(v - __half2float(h));
}

__global__ void k_convX(const float* __restrict__ x, __half* __restrict__ act) {
    int idx = blockIdx.x * blockDim.x + threadIdx.x;
    if (idx >= MTOT * 32) return;
    int m = idx >> 5, c4 = (idx & 31) << 2;
    float4 v = *reinterpret_cast<const float4*>(x + (size_t)m * 128 + c4);
    uint2 p;
    p.x = pkh2(v.x, v.y);
    p.y = pkh2(v.z, v.w);
    *reinterpret_cast<uint2*>((char*)act + ((size_t)m * 128 + c4) * 2) = p;
}

// ---------------- aggregation + activation ----------------------------------
template <int CPL, int ACT, int YH16>
__global__ void k_aggact(const void* __restrict__ yhp, const __half* __restrict__ yx,
                         int Nout, __half* __restrict__ oact, float* __restrict__ of32) {
    int node = blockIdx.x * 8 + (threadIdx.x >> 5);
    if (node >= MTOT) return;
    int lane = threadIdx.x & 31;
    int col = lane * CPL;
    float acc[CPL];
#pragma unroll
    for (int i = 0; i < CPL; i++) acc[i] = 0.f;
    int e0 = g_off[node], e1 = g_off[node + 1];
    const char* yxb = (const char*)yx;
    int e = e0;

    if constexpr (CPL == 8) {
        for (; e + 4 <= e1; e += 4) {
            int j0 = g_csrc[e], j1 = g_csrc[e + 1], j2 = g_csrc[e + 2], j3 = g_csrc[e + 3];
            uint4 p0 = *reinterpret_cast<const uint4*>(yxb + ((size_t)j0 * Nout + col) * 2);
            uint4 p1 = *reinterpret_cast<const uint4*>(yxb + ((size_t)j1 * Nout + col) * 2);
            uint4 p2 = *reinterpret_cast<const uint4*>(yxb + ((size_t)j2 * Nout + col) * 2);
            uint4 p3 = *reinterpret_cast<const uint4*>(yxb + ((size_t)j3 * Nout + col) * 2);
            uint32_t w0[4] = {p0.x, p0.y, p0.z, p0.w};
            uint32_t w1[4] = {p1.x, p1.y, p1.z, p1.w};
            uint32_t w2[4] = {p2.x, p2.y, p2.z, p2.w};
            uint32_t w3[4] = {p3.x, p3.y, p3.z, p3.w};
#pragma unroll
            for (int q = 0; q < 4; q++) {
                float2 f0 = __half22float2(*reinterpret_cast<__half2*>(&w0[q]));
                float2 f1 = __half22float2(*reinterpret_cast<__half2*>(&w1[q]));
                float2 f2 = __half22float2(*reinterpret_cast<__half2*>(&w2[q]));
                float2 f3 = __half22float2(*reinterpret_cast<__half2*>(&w3[q]));
                acc[2 * q]     += (f0.x + f1.x) + (f2.x + f3.x);
                acc[2 * q + 1] += (f0.y + f1.y) + (f2.y + f3.y);
            }
        }
        for (; e < e1; e++) {
            int j0 = g_csrc[e];
            uint4 p0 = *reinterpret_cast<const uint4*>(yxb + ((size_t)j0 * Nout + col) * 2);
            uint32_t w0[4] = {p0.x, p0.y, p0.z, p0.w};
#pragma unroll
            for (int q = 0; q < 4; q++) {
                float2 f0 = __half22float2(*reinterpret_cast<__half2*>(&w0[q]));
                acc[2 * q] += f0.x; acc[2 * q + 1] += f0.y;
            }
        }
    } else {
        for (; e + 4 <= e1; e += 4) {
            int j0 = g_csrc[e], j1 = g_csrc[e + 1], j2 = g_csrc[e + 2], j3 = g_csrc[e + 3];
            uint2 p0 = *reinterpret_cast<const uint2*>(yxb + ((size_t)j0 * Nout + col) * 2);
            uint2 p1 = *reinterpret_cast<const uint2*>(yxb + ((size_t)j1 * Nout + col) * 2);
            uint2 p2 = *reinterpret_cast<const uint2*>(yxb + ((size_t)j2 * Nout + col) * 2);
            uint2 p3 = *reinterpret_cast<const uint2*>(yxb + ((size_t)j3 * Nout + col) * 2);
            uint32_t w0[2] = {p0.x, p0.y};
            uint32_t w1[2] = {p1.x, p1.y};
            uint32_t w2[2] = {p2.x, p2.y};
            uint32_t w3[2] = {p3.x, p3.y};
#pragma unroll
            for (int q = 0; q < 2; q++) {
                float2 f0 = __half22float2(*reinterpret_cast<__half2*>(&w0[q]));
                float2 f1 = __half22float2(*reinterpret_cast<__half2*>(&w1[q]));
                float2 f2 = __half22float2(*reinterpret_cast<__half2*>(&w2[q]));
                float2 f3 = __half22float2(*reinterpret_cast<__half2*>(&w3[q]));
                acc[2 * q]     += (f0.x + f1.x) + (f2.x + f3.x);
                acc[2 * q + 1] += (f0.y + f1.y) + (f2.y + f3.y);
            }
        }
        for (; e < e1; e++) {
            int j0 = g_csrc[e];
            uint2 p0 = *reinterpret_cast<const uint2*>(yxb + ((size_t)j0 * Nout + col) * 2);
            uint32_t w0[2] = {p0.x, p0.y};
#pragma unroll
            for (int q = 0; q < 2; q++) {
                float2 f0 = __half22float2(*reinterpret_cast<__half2*>(&w0[q]));
                acc[2 * q] += f0.x; acc[2 * q + 1] += f0.y;
            }
        }
    }

    float dv = g_dinv[node];
    float v[CPL];
    if constexpr (YH16) {
        const char* yhb = (const char*)yhp;
        if constexpr (CPL == 8) {
            uint4 y = *reinterpret_cast<const uint4*>(yhb + ((size_t)node * Nout + col) * 2);
            uint32_t yw[4] = {y.x, y.y, y.z, y.w};
#pragma unroll
            for (int q = 0; q < 4; q++) {
                float2 f = __half22float2(*reinterpret_cast<__half2*>(&yw[q]));
                v[2 * q]     = f.x - dv * acc[2 * q];
                v[2 * q + 1] = f.y - dv * acc[2 * q + 1];
            }
        } else {
            uint2 y = *reinterpret_cast<const uint2*>(yhb + ((size_t)node * Nout + col) * 2);
            uint32_t yw[2] = {y.x, y.y};
#pragma unroll
            for (int q = 0; q < 2; q++) {
                float2 f = __half22float2(*reinterpret_cast<__half2*>(&yw[q]));
                v[2 * q]     = f.x - dv * acc[2 * q];
                v[2 * q + 1] = f.y - dv * acc[2 * q + 1];
            }
        }
    } else {
        const float* yh = (const float*)yhp;
#pragma unroll
        for (int i = 0; i < CPL; i += 4) {
            float4 y = *reinterpret_cast<const float4*>(yh + (size_t)node * Nout + col + i);
            v[i + 0] = y.x - dv * acc[i + 0];
            v[i + 1] = y.y - dv * acc[i + 1];
            v[i + 2] = y.z - dv * acc[i + 2];
            v[i + 3] = y.w - dv * acc[i + 3];
        }
    }
    if constexpr (ACT) {
#pragma unroll
        for (int i = 0; i < CPL; i++) v[i] = tanha(v[i]);
        size_t wo = ((size_t)node * Nout + col) * 2;
        if constexpr (CPL == 8) {
            uint4 p;
            p.x = pkh2(v[0], v[1]); p.y = pkh2(v[2], v[3]);
            p.z = pkh2(v[4], v[5]); p.w = pkh2(v[6], v[7]);
            *reinterpret_cast<uint4*>((char*)oact + wo) = p;
        } else {
            uint2 p;
            p.x = pkh2(v[0], v[1]); p.y = pkh2(v[2], v[3]);
            *reinterpret_cast<uint2*>((char*)oact + wo) = p;
        }
    } else {
#pragma unroll
        for (int i = 0; i < CPL; i += 4) {
            float4 o = make_float4(v[i], v[i + 1], v[i + 2], v[i + 3]);
            *reinterpret_cast<float4*>(of32 + (size_t)node * Nout + col + i) = o;
        }
    }
}

// ---------------- tcgen05 dual-output fp16 GEMM ------------------------------
// One CTA = 128 rows; yh = act@Wh + b (TMEM [0,256)), yx = dinv*(act@Wx) ([256,512)).
// 3-stage B pipeline with cp.async fills; A slots 2x16KB @0/@16K; B @32K+(s%3)*64K.
__global__ void __launch_bounds__(256, 1) k_gemm_tc(
    const __half* __restrict__ act, int K,
    const __half* __restrict__ Whi, const __half* __restrict__ Wlo,
    const float* __restrict__ bias, int Nout, uint32_t idesc,
    float* __restrict__ yhf32, __half* __restrict__ yh16, __half* __restrict__ yx)
{
#if TC_OK
    extern __shared__ char smraw[];
    __shared__ __align__(16) uint32_t ctrl[8];  // [0]=tmem ptr; mbars at +8,+16,+24
    int tid = threadIdx.x, wid = tid >> 5;
    uint32_t cu = smem_u32(ctrl);

    if (wid == 0) {
        asm volatile("tcgen05.alloc.cta_group::1.sync.aligned.shared::cta.b32 [%0], %1;"
                     :: "r"(cu), "r"(512u) : "memory");
        asm volatile("tcgen05.relinquish_alloc_permit.cta_group::1.sync.aligned;");
    }
    if (tid == 0) { mbar_init(cu + 8, 1); mbar_init(cu + 16, 1); mbar_init(cu + 24, 1); }
    __syncthreads();
    uint32_t tmem;
    asm("ld.shared.b32 %0, [%1];" : "=r"(tmem) : "r"(cu));

    uint32_t raw = smem_u32(smraw);
    uint32_t sb = (raw + 1023) & ~1023u;
    char* sm = smraw + (sb - raw);

    int m0 = blockIdx.x * 128;
    const char* Ab = (const char*)act;
    int NS = (K >> 6) * 2;
    int nbB = Nout << 3;
    int loOfs = Nout << 7;

    for (int s = 0; s < NS; s++) {
        int kc = s >> 1, out = s & 1, buf = s % 3;
        uint32_t bstu = sb + 32768 + buf * 65536;
        if (s >= 3) {
            int idx = (s - 3 - buf) / 3;
            mbar_wait(cu + 8 + buf * 8, idx & 1);
        }

        if (out == 0) {
            uint32_t astu = sb + (kc & 1) * 16384;
            char* ast = sm + (kc & 1) * 16384;
            for (int i = tid; i < 1024; i += 256) {
                int row = i >> 3, c = i & 7;
                int m = m0 + row;
                uint32_t bo = (row << 7) + (c << 4);
                uint32_t so = bo ^ ((bo >> 3) & 0x70);
                if (m < MTOT) {
                    CPA16(astu + so, Ab + ((size_t)m * K + (kc << 6) + (c << 3)) * 2);
                } else {
                    *reinterpret_cast<uint4*>(ast + so) = make_uint4(0, 0, 0, 0);
                }
            }
        }
        {
            size_t wofs = (size_t)out * Nout * K;
            const char* Bh = (const char*)(Whi + wofs);
            const char* Bl = (const char*)(Wlo + wofs);
            for (int i = tid; i < nbB; i += 256) {
                int n = i >> 3, c = i & 7;
                size_t go = ((size_t)n * K + (kc << 6) + (c << 3)) * 2;
                uint32_t bo = (n << 7) + (c << 4);
                uint32_t so = bo ^ ((bo >> 3) & 0x70);
                CPA16(bstu + so, Bh + go);
                CPA16(bstu + loOfs + so, Bl + go);
            }
        }
        CPA_COMMIT();
        CPA_WAIT0();
        asm volatile("fence.proxy.async.shared::cta;" ::: "memory");
        __syncthreads();

        if (wid == 0 && elect1()) {
            uint64_t dA  = mk_desc(sb + (kc & 1) * 16384);
            uint64_t dBh = mk_desc(bstu);
            uint64_t dBl = mk_desc(bstu + loOfs);
            uint32_t D = tmem + out * 256;
#pragma unroll
            for (int k = 0; k < 4; k++) {
                uint64_t o = (uint64_t)(k * 2);
                mma_ss_f16(D, dA + o, dBh + o, idesc, (uint32_t)((kc | k) != 0));
                mma_ss_f16(D, dA + o, dBl + o, idesc, 1u);
            }
            asm volatile("tcgen05.commit.cta_group::1.mbarrier::arrive::one.shared::cluster.b64 [%0];"
                         :: "r"(cu + 8 + buf * 8) : "memory");
        }
    }

    for (int s = (NS >= 3 ? NS - 3 : 0); s < NS; s++) {
        int b = s % 3;
        int idx = (s - b) / 3;
        mbar_wait(cu + 8 + b * 8, idx & 1);
    }
    asm volatile("tcgen05.fence::after_thread_sync;" ::: "memory");

    int lane = tid & 31, sub = wid & 3, wg = wid >> 2;
    int m = m0 + sub * 32 + lane;
    int niter = Nout >> 5;
    uint32_t base = tmem + wg * 256;
    for (int cc = 0; cc < niter; cc++) {
        uint32_t r[32];
        LDTM32(r, base + cc * 32);
        asm volatile("tcgen05.wait::ld.sync.aligned;" ::: "memory");
        if (m < MTOT) {
            int nb = cc * 32;
            if (wg == 0) {
                if (yh16) {
                    uint32_t hp[16];
#pragma unroll
                    for (int q = 0; q < 16; q++)
                        hp[q] = pkh2(__uint_as_float(r[2 * q])     + bias[nb + 2 * q],
                                     __uint_as_float(r[2 * q + 1]) + bias[nb + 2 * q + 1]);
                    uint4* dp = reinterpret_cast<uint4*>((char*)yh16 + ((size_t)m * Nout + nb) * 2);
#pragma unroll
                    for (int q = 0; q < 4; q++)
                        dp[q] = make_uint4(hp[4 * q], hp[4 * q + 1], hp[4 * q + 2], hp[4 * q + 3]);
                } else {
                    float4* dp = reinterpret_cast<float4*>(yhf32 + (size_t)m * Nout + nb);
#pragma unroll
                    for (int q = 0; q < 8; q++) {
                        float4 v;
                        v.x = __uint_as_float(r[q * 4 + 0]) + bias[nb + q * 4 + 0];
                        v.y = __uint_as_float(r[q * 4 + 1]) + bias[nb + q * 4 + 1];
                        v.z = __uint_as_float(r[q * 4 + 2]) + bias[nb + q * 4 + 2];
                        v.w = __uint_as_float(r[q * 4 + 3]) + bias[nb + q * 4 + 3];
                        dp[q] = v;
                    }
                }
            } else {
                float dv = g_dinv[m];
                uint32_t hp[16];
#pragma unroll
                for (int q = 0; q < 16; q++)
                    hp[q] = pkh2(dv * __uint_as_float(r[2 * q]),
                                 dv * __uint_as_float(r[2 * q + 1]));
                uint4* dp = reinterpret_cast<uint4*>((char*)yx + ((size_t)m * Nout + nb) * 2);
#pragma unroll
                for (int q = 0; q < 4; q++)
                    dp[q] = make_uint4(hp[4 * q], hp[4 * q + 1], hp[4 * q + 2], hp[4 * q + 3]);
            }
        }
    }
    __syncthreads();
    if (wid == 0) {
        asm volatile("tcgen05.dealloc.cta_group::1.sync.aligned.b32 %0, %1;"
                     :: "r"(tmem), "r"(512u));
    }
#endif  // TC_OK
}

// ---------------- SIMT fallback GEMM (non-"a" passes only) -------------------
__global__ void __launch_bounds__(256) k_gemm_fb(
    const __half* __restrict__ act, int K,
    const __half* __restrict__ Whi, const __half* __restrict__ Wlo,
    const float* __restrict__ bias, int Nout, uint32_t idesc,
    float* __restrict__ yhf32, __half* __restrict__ yh16, __half* __restrict__ yx)
{
#if !TC_OK
    __shared__ float As[16][132];
    __shared__ float Bs[16][128];
    int tid = threadIdx.x;
    int tx = tid & 15, ty = tid >> 4;
    int m0 = blockIdx.x * 128;
    size_t hofs = (size_t)blockIdx.y * Nout * K;
    const __half* Bh = Whi + hofs;
    const __half* Bl = Wlo + hofs;

    for (int n0 = 0; n0 < Nout; n0 += 128) {
        float acc[8][8];
#pragma unroll
        for (int i = 0; i < 8; i++)
#pragma unroll
            for (int j = 0; j < 8; j++) acc[i][j] = 0.f;

        for (int k0 = 0; k0 < K; k0 += 16) {
            for (int i = tid; i < 2048; i += 256) {
                int r = i >> 4, k = i & 15;
                int m = m0 + r;
                As[k][r] = (m < MTOT) ? __half2float(act[(size_t)m * K + k0 + k]) : 0.f;
            }
            for (int i = tid; i < 2048; i += 256) {
                int r = i >> 4, k = i & 15;
                size_t o = (size_t)(n0 + r) * K + k0 + k;
                Bs[k][r] = __half2float(Bh[o]) + __half2float(Bl[o]);
            }
            __syncthreads();
#pragma unroll
            for (int k = 0; k < 16; k++) {
                float a[8], b[8];
#pragma unroll
                for (int i = 0; i < 8; i++) a[i] = As[k][ty * 8 + i];
#pragma unroll
                for (int j = 0; j < 8; j++) b[j] = Bs[k][tx * 8 + j];
#pragma unroll
                for (int i = 0; i < 8; i++)
#pragma unroll
                    for (int j = 0; j < 8; j++) acc[i][j] += a[i] * b[j];
            }
            __syncthreads();
        }

#pragma unroll
        for (int i = 0; i < 8; i++) {
            int m = m0 + ty * 8 + i;
            if (m >= MTOT) continue;
            float dv = g_dinv[m];
#pragma unroll
            for (int j = 0; j < 8; j++) {
                int n = n0 + tx * 8 + j;
                if (blockIdx.y == 0) {
                    float v = acc[i][j] + bias[n];
                    if (yh16) yh16[(size_t)m * Nout + n] = __float2half_rn(v);
                    else      yhf32[(size_t)m * Nout + n] = v;
                } else {
                    yx[(size_t)m * Nout + n] = __float2half_rn(dv * acc[i][j]);
                }
            }
        }
        __syncthreads();
    }
#endif  // !TC_OK
}

// ---------------- launch -----------------------------------------------------
static inline uint32_t mk_idesc(int N) {
    return (1u << 4) | ((uint32_t)(N / 8) << 17) | (8u << 24);
}

extern "C" void kernel_launch(void* const* d_in, const int* in_sizes, int n_in,
                              void* d_out, int out_size) {
    const float* x   = (const float*)d_in[0];
    const int*   src = (const int*)d_in[1];
    const int*   dst = (const int*)d_in[2];
    const float* W1  = (const float*)d_in[3];
    const float* b1  = (const float*)d_in[4];
    const float* W2  = (const float*)d_in[5];
    const float* b2  = (const float*)d_in[6];
    const float* W3  = (const float*)d_in[7];
    const float* b3  = (const float*)d_in[8];
    float* out = (float*)d_out;

    void* p;
    cudaGetSymbolAddress(&p, g_act);  __half* act  = (__half*)p;
    cudaGetSymbolAddress(&p, g_yh);   float*  yhf  = (float*)p;
    __half* yhh = (__half*)yhf;
    cudaGetSymbolAddress(&p, g_yx);   __half* yx   = (__half*)p;
    cudaGetSymbolAddress(&p, g_Whi);  __half* Whi  = (__half*)p;
    cudaGetSymbolAddress(&p, g_Wlo);  __half* Wlo  = (__half*)p;
    void* degp; cudaGetSymbolAddress(&degp, g_deg);

    cudaFuncSetAttribute(k_gemm_tc, cudaFuncAttributeMaxDynamicSharedMemorySize, 231424);

    static cudaStream_t s2 = nullptr;
    static cudaEvent_t evFork = nullptr, evJoin = nullptr;
    if (!s2) {
        cudaStreamCreateWithFlags(&s2, cudaStreamNonBlocking);
        cudaEventCreateWithFlags(&evFork, cudaEventDisableTiming);
        cudaEventCreateWithFlags(&evJoin, cudaEventDisableTiming);
    }

    uint32_t id256 = mk_idesc(256), id128 = mk_idesc(128);
    int gg = (MTOT + 127) / 128;     // 391
    dim3 ggfb(gg, 2);
    int gs = (MTOT + 7) / 8;         // 6250
    size_t shm = 231424;

    auto gemm = [&](int K, const __half* bh, const __half* bl,
                    const float* bias, int Nout, uint32_t idesc, __half* y16) {
        k_gemm_tc<<<gg, 256, shm>>>(act, K, bh, bl, bias, Nout, idesc,
                                    y16 ? nullptr : yhf, y16, yx);
        k_gemm_fb<<<ggfb, 256>>>(act, K, bh, bl, bias, Nout, idesc,
                                 y16 ? nullptr : yhf, y16, yx);
    };

    // ---- fork: CSR build + W2/W3 conversion on s2  ||  W1+X conv + L1 GEMM on main ----
    // L1's GEMM needs only act (convX) and W1; CSR is first needed by L1's agg.
    cudaEventRecord(evFork, 0);
    cudaStreamWaitEvent(s2, evFork, 0);

    int nblk = (MTOT + 1023) / 1024;  // 49
    cudaMemsetAsync(degp, 0, MTOT * sizeof(int), s2);
    k_count<<<(NE + 255) / 256, 256, 0, s2>>>(dst);
    k_scan1<<<nblk, 1024, 0, s2>>>();
    k_scan2<<<1, 64, 0, s2>>>(nblk);
    k_scan3<<<nblk, 1024, 0, s2>>>();
    k_scatter<<<(NE + 255) / 256, 256, 0, s2>>>(src, dst);
    k_convW2<<<(512 * 256 + 255) / 256, 256, 0, s2>>>(W2, 256, 256, Whi + 65536, Wlo + 65536);
    k_convW2<<<(512 * 128 + 255) / 256, 256, 0, s2>>>(W3, 256, 128, Whi + 196608, Wlo + 196608);
    cudaEventRecord(evJoin, s2);

    // main stream: W1 conversion + input conversion + L1 GEMM (no CSR dependency)
    k_convW2<<<(256 * 256 + 255) / 256, 256>>>(W1, 128, 256, Whi, Wlo);
    k_convX<<<(MTOT * 32 + 255) / 256, 256>>>(x, act);
    gemm(128, Whi, Wlo, b1, 256, id256, yhh);

    // join: L1 agg needs CSR
    cudaStreamWaitEvent(0, evJoin, 0);
    k_aggact<8, 1, 1><<<gs, 256>>>(yhh, yx, 256, act, nullptr);

    // L2-4: K=256, Nout=256 (shared W2), fp16 yh
    for (int l = 0; l < 3; l++) {
        gemm(256, Whi + 65536, Wlo + 65536, b2, 256, id256, yhh);
        k_aggact<8, 1, 1><<<gs, 256>>>(yhh, yx, 256, act, nullptr);
    }
    // L5: K=256, Nout=128; fp32 yh, final out, no tanh
    gemm(256, Whi + 196608, Wlo + 196608, b3, 128, id128, nullptr);
    k_aggact<4, 0, 0><<<gs, 256>>>(yhf, yx, 128, nullptr, out);
}

// round 13
// speedup vs baseline: 2.4332x; 1.0553x over previous
#include <cuda_runtime.h>
#include <cuda_bf16.h>
#include <cuda_fp16.h>
#include <stdint.h>
#include <math.h>

#define MTOT 50000
#define NE   800000

#if defined(__CUDA_ARCH_FEAT_SM103_ALL) || defined(__CUDA_ARCH_FEAT_SM100_ALL) || \
    defined(__CUDA_ARCH_FEAT_SM101_ALL) || defined(__CUDA_ARCH_FEAT_SM110_ALL)
#define TC_OK 1
#else
#define TC_OK 0
#endif

// ---------------- device scratch (no cudaMalloc) ----------------------------
__device__ __align__(16) __half g_act[(size_t)MTOT * 256];
__device__ __align__(16) float  g_yh[(size_t)MTOT * 256];   // fp32 L5; fp16 view L1-4
__device__ __align__(16) __half g_yx[(size_t)MTOT * 256];
__device__ __align__(16) __half g_Whi[262144];
__device__ __align__(16) __half g_Wlo[262144];
__device__ float g_dinv[MTOT];
__device__ int   g_deg[MTOT];
__device__ int   g_off[MTOT + 1];
__device__ int   g_cur[MTOT];
__device__ int   g_csrc[NE];
__device__ int   g_bsum[64];

// ---------------- small helpers ---------------------------------------------
__device__ __forceinline__ uint32_t smem_u32(const void* p) {
    uint32_t a;
    asm("{ .reg .u64 t; cvta.to.shared.u64 t, %1; cvt.u32.u64 %0, t; }" : "=r"(a) : "l"(p));
    return a;
}
__device__ __forceinline__ bool elect1() {
    uint32_t p;
    asm volatile("{\n\t.reg .pred p;\n\telect.sync _|p, 0xFFFFFFFF;\n\tselp.b32 %0,1,0,p;\n\t}" : "=r"(p));
    return p != 0;
}
__device__ __forceinline__ void mbar_init(uint32_t mbar, uint32_t cnt) {
    asm volatile("mbarrier.init.shared.b64 [%0], %1;" :: "r"(mbar), "r"(cnt) : "memory");
}
__device__ __forceinline__ void mbar_wait(uint32_t mbar, uint32_t parity) {
    uint32_t done;
    asm volatile("{\n\t.reg .pred p;\n\tmbarrier.try_wait.parity.acquire.cta.shared::cta.b64 p, [%1], %2;\n\tselp.b32 %0,1,0,p;\n\t}"
                 : "=r"(done) : "r"(mbar), "r"(parity) : "memory");
    if (!done) {
        asm volatile("{\n\t.reg .pred P1;\nWL_%=:\n\tmbarrier.try_wait.parity.acquire.cta.shared::cta.b64 P1, [%0], %1, 0x989680;\n\t@P1 bra.uni WD_%=;\n\tbra.uni WL_%=;\nWD_%=:\n\t}"
                     :: "r"(mbar), "r"(parity) : "memory");
    }
}
__device__ __forceinline__ float tanha(float x) {
    float y; asm("tanh.approx.f32 %0, %1;" : "=f"(y) : "f"(x)); return y;
}
__device__ __forceinline__ uint32_t pkh2(float a, float b) {
    __half2 h = __floats2half2_rn(a, b);
    return *reinterpret_cast<uint32_t*>(&h);
}
#define CPA16(sm_u32, gptr) \
    asm volatile("cp.async.cg.shared.global [%0], [%1], 16;" :: "r"(sm_u32), "l"(gptr) : "memory")
#define CPA_COMMIT() asm volatile("cp.async.commit_group;" ::: "memory")
#define CPA_WAIT0()  asm volatile("cp.async.wait_group 0;" ::: "memory")
#define CPA_WAIT1()  asm volatile("cp.async.wait_group 1;" ::: "memory")

#if TC_OK
__device__ __forceinline__ uint64_t mk_desc(uint32_t addr) {
    // SW128, version=1(Blackwell), SBO=64, LBO=1, start=addr>>4
    return 0x4000404000010000ULL | ((uint64_t)(addr >> 4) & 0x3FFF);
}
__device__ __forceinline__ void mma_ss_f16(uint32_t d, uint64_t ad, uint64_t bd,
                                           uint32_t idesc, uint32_t en) {
    asm volatile("{\n\t.reg .pred p;\n\tsetp.ne.u32 p, %4, 0;\n\t"
                 "tcgen05.mma.cta_group::1.kind::f16 [%0], %1, %2, %3, {%5,%5,%5,%5}, p;\n\t}"
                 :: "r"(d), "l"(ad), "l"(bd), "r"(idesc), "r"(en), "r"(0u) : "memory");
}
#define LDTM32(r, addr) \
    asm volatile("tcgen05.ld.sync.aligned.32x32b.x32.b32 " \
        "{%0,%1,%2,%3,%4,%5,%6,%7,%8,%9,%10,%11,%12,%13,%14,%15," \
        "%16,%17,%18,%19,%20,%21,%22,%23,%24,%25,%26,%27,%28,%29,%30,%31}, [%32];" \
        : "=r"((r)[0]),"=r"((r)[1]),"=r"((r)[2]),"=r"((r)[3]),"=r"((r)[4]),"=r"((r)[5]),"=r"((r)[6]),"=r"((r)[7]), \
          "=r"((r)[8]),"=r"((r)[9]),"=r"((r)[10]),"=r"((r)[11]),"=r"((r)[12]),"=r"((r)[13]),"=r"((r)[14]),"=r"((r)[15]), \
          "=r"((r)[16]),"=r"((r)[17]),"=r"((r)[18]),"=r"((r)[19]),"=r"((r)[20]),"=r"((r)[21]),"=r"((r)[22]),"=r"((r)[23]), \
          "=r"((r)[24]),"=r"((r)[25]),"=r"((r)[26]),"=r"((r)[27]),"=r"((r)[28]),"=r"((r)[29]),"=r"((r)[30]),"=r"((r)[31]) \
        : "r"(addr))
#endif

// ---------------- CSR build (parallel scan) ----------------------------------
__global__ void k_count(const int* __restrict__ dst) {
    int e = blockIdx.x * blockDim.x + threadIdx.x;
    if (e < NE) atomicAdd(&g_deg[dst[e]], 1);
}
__global__ void k_scan1() {
    __shared__ int sh[1024];
    int t = threadIdx.x;
    int i = blockIdx.x * 1024 + t;
    int v = (i < MTOT) ? g_deg[i] : 0;
    sh[t] = v;
    __syncthreads();
    for (int ofs = 1; ofs < 1024; ofs <<= 1) {
        int x = (t >= ofs) ? sh[t - ofs] : 0;
        __syncthreads();
        sh[t] += x;
        __syncthreads();
    }
    if (i < MTOT) g_off[i] = sh[t] - v;
    if (t == 1023) g_bsum[blockIdx.x] = sh[1023];
}
__global__ void k_scan2(int nblk) {
    __shared__ int sh[64];
    int t = threadIdx.x;
    int v = (t < nblk) ? g_bsum[t] : 0;
    sh[t] = v;
    __syncthreads();
    for (int ofs = 1; ofs < 64; ofs <<= 1) {
        int x = (t >= ofs) ? sh[t - ofs] : 0;
        __syncthreads();
        sh[t] += x;
        __syncthreads();
    }
    if (t < nblk) g_bsum[t] = sh[t] - v;
}
__global__ void k_scan3() {
    int i = blockIdx.x * 1024 + threadIdx.x;
    if (i < MTOT) {
        int o = g_off[i] + g_bsum[i >> 10];
        g_off[i] = o;
        g_cur[i] = o;
        int d = g_deg[i];
        g_dinv[i] = (d > 0) ? rsqrtf((float)d) : 0.0f;
    }
    if (i == 0) g_off[MTOT] = NE;
}
__global__ void k_scatter(const int* __restrict__ src, const int* __restrict__ dst) {
    int e = blockIdx.x * blockDim.x + threadIdx.x;
    if (e < NE) {
        int p = atomicAdd(&g_cur[dst[e]], 1);
        g_csrc[p] = src[e];
    }
}

// ---------------- converters ------------------------------------------------
__global__ void k_convW2(const float* __restrict__ W, int F, int N,
                         __half* __restrict__ oh, __half* __restrict__ ol) {
    int idx = blockIdx.x * blockDim.x + threadIdx.x;
    if (idx >= 2 * F * N) return;
    int k2 = idx / N, n = idx % N;
    int half = (k2 >= F);
    int k = k2 - half * F;
    float v = W[(size_t)k2 * N + n];
    __half h = __float2half_rn(v);
    size_t o = (size_t)half * N * F + (size_t)n * F + k;
    oh[o] = h;
    ol[o] = __float2half_rn(v - __half2float(h));
}

__global__ void k_convX(const float* __restrict__ x, __half* __restrict__ act) {
    int idx = blockIdx.x * blockDim.x + threadIdx.x;
    if (idx >= MTOT * 32) return;
    int m = idx >> 5, c4 = (idx & 31) << 2;
    float4 v = *reinterpret_cast<const float4*>(x + (size_t)m * 128 + c4);
    uint2 p;
    p.x = pkh2(v.x, v.y);
    p.y = pkh2(v.z, v.w);
    *reinterpret_cast<uint2*>((char*)act + ((size_t)m * 128 + c4) * 2) = p;
}

// ---------------- aggregation + activation ----------------------------------
template <int CPL, int ACT, int YH16>
__global__ void k_aggact(const void* __restrict__ yhp, const __half* __restrict__ yx,
                         int Nout, __half* __restrict__ oact, float* __restrict__ of32) {
    int node = blockIdx.x * 8 + (threadIdx.x >> 5);
    if (node >= MTOT) return;
    int lane = threadIdx.x & 31;
    int col = lane * CPL;
    float acc[CPL];
#pragma unroll
    for (int i = 0; i < CPL; i++) acc[i] = 0.f;
    int e0 = g_off[node], e1 = g_off[node + 1];
    const char* yxb = (const char*)yx;
    int e = e0;

    if constexpr (CPL == 8) {
        for (; e + 4 <= e1; e += 4) {
            int j0 = g_csrc[e], j1 = g_csrc[e + 1], j2 = g_csrc[e + 2], j3 = g_csrc[e + 3];
            uint4 p0 = *reinterpret_cast<const uint4*>(yxb + ((size_t)j0 * Nout + col) * 2);
            uint4 p1 = *reinterpret_cast<const uint4*>(yxb + ((size_t)j1 * Nout + col) * 2);
            uint4 p2 = *reinterpret_cast<const uint4*>(yxb + ((size_t)j2 * Nout + col) * 2);
            uint4 p3 = *reinterpret_cast<const uint4*>(yxb + ((size_t)j3 * Nout + col) * 2);
            uint32_t w0[4] = {p0.x, p0.y, p0.z, p0.w};
            uint32_t w1[4] = {p1.x, p1.y, p1.z, p1.w};
            uint32_t w2[4] = {p2.x, p2.y, p2.z, p2.w};
            uint32_t w3[4] = {p3.x, p3.y, p3.z, p3.w};
#pragma unroll
            for (int q = 0; q < 4; q++) {
                float2 f0 = __half22float2(*reinterpret_cast<__half2*>(&w0[q]));
                float2 f1 = __half22float2(*reinterpret_cast<__half2*>(&w1[q]));
                float2 f2 = __half22float2(*reinterpret_cast<__half2*>(&w2[q]));
                float2 f3 = __half22float2(*reinterpret_cast<__half2*>(&w3[q]));
                acc[2 * q]     += (f0.x + f1.x) + (f2.x + f3.x);
                acc[2 * q + 1] += (f0.y + f1.y) + (f2.y + f3.y);
            }
        }
        for (; e < e1; e++) {
            int j0 = g_csrc[e];
            uint4 p0 = *reinterpret_cast<const uint4*>(yxb + ((size_t)j0 * Nout + col) * 2);
            uint32_t w0[4] = {p0.x, p0.y, p0.z, p0.w};
#pragma unroll
            for (int q = 0; q < 4; q++) {
                float2 f0 = __half22float2(*reinterpret_cast<__half2*>(&w0[q]));
                acc[2 * q] += f0.x; acc[2 * q + 1] += f0.y;
            }
        }
    } else {
        for (; e + 4 <= e1; e += 4) {
            int j0 = g_csrc[e], j1 = g_csrc[e + 1], j2 = g_csrc[e + 2], j3 = g_csrc[e + 3];
            uint2 p0 = *reinterpret_cast<const uint2*>(yxb + ((size_t)j0 * Nout + col) * 2);
            uint2 p1 = *reinterpret_cast<const uint2*>(yxb + ((size_t)j1 * Nout + col) * 2);
            uint2 p2 = *reinterpret_cast<const uint2*>(yxb + ((size_t)j2 * Nout + col) * 2);
            uint2 p3 = *reinterpret_cast<const uint2*>(yxb + ((size_t)j3 * Nout + col) * 2);
            uint32_t w0[2] = {p0.x, p0.y};
            uint32_t w1[2] = {p1.x, p1.y};
            uint32_t w2[2] = {p2.x, p2.y};
            uint32_t w3[2] = {p3.x, p3.y};
#pragma unroll
            for (int q = 0; q < 2; q++) {
                float2 f0 = __half22float2(*reinterpret_cast<__half2*>(&w0[q]));
                float2 f1 = __half22float2(*reinterpret_cast<__half2*>(&w1[q]));
                float2 f2 = __half22float2(*reinterpret_cast<__half2*>(&w2[q]));
                float2 f3 = __half22float2(*reinterpret_cast<__half2*>(&w3[q]));
                acc[2 * q]     += (f0.x + f1.x) + (f2.x + f3.x);
                acc[2 * q + 1] += (f0.y + f1.y) + (f2.y + f3.y);
            }
        }
        for (; e < e1; e++) {
            int j0 = g_csrc[e];
            uint2 p0 = *reinterpret_cast<const uint2*>(yxb + ((size_t)j0 * Nout + col) * 2);
            uint32_t w0[2] = {p0.x, p0.y};
#pragma unroll
            for (int q = 0; q < 2; q++) {
                float2 f0 = __half22float2(*reinterpret_cast<__half2*>(&w0[q]));
                acc[2 * q] += f0.x; acc[2 * q + 1] += f0.y;
            }
        }
    }

    float dv = g_dinv[node];
    float v[CPL];
    if constexpr (YH16) {
        const char* yhb = (const char*)yhp;
        if constexpr (CPL == 8) {
            uint4 y = *reinterpret_cast<const uint4*>(yhb + ((size_t)node * Nout + col) * 2);
            uint32_t yw[4] = {y.x, y.y, y.z, y.w};
#pragma unroll
            for (int q = 0; q < 4; q++) {
                float2 f = __half22float2(*reinterpret_cast<__half2*>(&yw[q]));
                v[2 * q]     = f.x - dv * acc[2 * q];
                v[2 * q + 1] = f.y - dv * acc[2 * q + 1];
            }
        } else {
            uint2 y = *reinterpret_cast<const uint2*>(yhb + ((size_t)node * Nout + col) * 2);
            uint32_t yw[2] = {y.x, y.y};
#pragma unroll
            for (int q = 0; q < 2; q++) {
                float2 f = __half22float2(*reinterpret_cast<__half2*>(&yw[q]));
                v[2 * q]     = f.x - dv * acc[2 * q];
                v[2 * q + 1] = f.y - dv * acc[2 * q + 1];
            }
        }
    } else {
        const float* yh = (const float*)yhp;
#pragma unroll
        for (int i = 0; i < CPL; i += 4) {
            float4 y = *reinterpret_cast<const float4*>(yh + (size_t)node * Nout + col + i);
            v[i + 0] = y.x - dv * acc[i + 0];
            v[i + 1] = y.y - dv * acc[i + 1];
            v[i + 2] = y.z - dv * acc[i + 2];
            v[i + 3] = y.w - dv * acc[i + 3];
        }
    }
    if constexpr (ACT) {
#pragma unroll
        for (int i = 0; i < CPL; i++) v[i] = tanha(v[i]);
        size_t wo = ((size_t)node * Nout + col) * 2;
        if constexpr (CPL == 8) {
            uint4 p;
            p.x = pkh2(v[0], v[1]); p.y = pkh2(v[2], v[3]);
            p.z = pkh2(v[4], v[5]); p.w = pkh2(v[6], v[7]);
            *reinterpret_cast<uint4*>((char*)oact + wo) = p;
        } else {
            uint2 p;
            p.x = pkh2(v[0], v[1]); p.y = pkh2(v[2], v[3]);
            *reinterpret_cast<uint2*>((char*)oact + wo) = p;
        }
    } else {
#pragma unroll
        for (int i = 0; i < CPL; i += 4) {
            float4 o = make_float4(v[i], v[i + 1], v[i + 2], v[i + 3]);
            *reinterpret_cast<float4*>(of32 + (size_t)node * Nout + col + i) = o;
        }
    }
}

// ---------------- tcgen05 dual-output fp16 GEMM ------------------------------
// One CTA = 128 rows; yh = act@Wh + b (TMEM [0,256)), yx = dinv*(act@Wx) ([256,512)).
// Software-pipelined: fills for stage s+1 are issued before waiting stage s, so
// LDGSTS traffic streams during MMA. A slots 2x16KB @0/@16K; B @32K+(s%3)*64K.
__global__ void __launch_bounds__(256, 1) k_gemm_tc(
    const __half* __restrict__ act, int K,
    const __half* __restrict__ Whi, const __half* __restrict__ Wlo,
    const float* __restrict__ bias, int Nout, uint32_t idesc,
    float* __restrict__ yhf32, __half* __restrict__ yh16, __half* __restrict__ yx)
{
#if TC_OK
    extern __shared__ char smraw[];
    __shared__ __align__(16) uint32_t ctrl[8];  // [0]=tmem ptr; mbars at +8,+16,+24
    int tid = threadIdx.x, wid = tid >> 5;
    uint32_t cu = smem_u32(ctrl);

    if (wid == 0) {
        asm volatile("tcgen05.alloc.cta_group::1.sync.aligned.shared::cta.b32 [%0], %1;"
                     :: "r"(cu), "r"(512u) : "memory");
        asm volatile("tcgen05.relinquish_alloc_permit.cta_group::1.sync.aligned;");
    }
    if (tid == 0) { mbar_init(cu + 8, 1); mbar_init(cu + 16, 1); mbar_init(cu + 24, 1); }
    __syncthreads();
    uint32_t tmem;
    asm("ld.shared.b32 %0, [%1];" : "=r"(tmem) : "r"(cu));

    uint32_t raw = smem_u32(smraw);
    uint32_t sb = (raw + 1023) & ~1023u;
    char* sm = smraw + (sb - raw);

    int m0 = blockIdx.x * 128;
    const char* Ab = (const char*)act;
    int NS = (K >> 6) * 2;
    int nbB = Nout << 3;
    int loOfs = Nout << 7;

    // fill helper expanded inline twice (prologue + steady state)
#define FILL_STAGE(S)                                                              \
    do {                                                                           \
        int kc_ = (S) >> 1, out_ = (S) & 1, buf_ = (S) % 3;                        \
        uint32_t bstu_ = sb + 32768 + buf_ * 65536;                                \
        if (out_ == 0) {                                                           \
            uint32_t astu_ = sb + (kc_ & 1) * 16384;                               \
            char* ast_ = sm + (kc_ & 1) * 16384;                                   \
            for (int i = tid; i < 1024; i += 256) {                                \
                int row_ = i >> 3, c_ = i & 7;                                     \
                int m_ = m0 + row_;                                                \
                uint32_t bo_ = (row_ << 7) + (c_ << 4);                            \
                uint32_t so_ = bo_ ^ ((bo_ >> 3) & 0x70);                          \
                if (m_ < MTOT) {                                                   \
                    CPA16(astu_ + so_, Ab + ((size_t)m_ * K + (kc_ << 6) + (c_ << 3)) * 2); \
                } else {                                                           \
                    *reinterpret_cast<uint4*>(ast_ + so_) = make_uint4(0, 0, 0, 0);\
                }                                                                  \
            }                                                                      \
        }                                                                          \
        size_t wofs_ = (size_t)out_ * Nout * K;                                    \
        const char* Bh_ = (const char*)(Whi + wofs_);                              \
        const char* Bl_ = (const char*)(Wlo + wofs_);                              \
        for (int i = tid; i < nbB; i += 256) {                                     \
            int n_ = i >> 3, c_ = i & 7;                                           \
            size_t go_ = ((size_t)n_ * K + (kc_ << 6) + (c_ << 3)) * 2;            \
            uint32_t bo_ = (n_ << 7) + (c_ << 4);                                  \
            uint32_t so_ = bo_ ^ ((bo_ >> 3) & 0x70);                              \
            CPA16(bstu_ + so_, Bh_ + go_);                                         \
            CPA16(bstu_ + loOfs + so_, Bl_ + go_);                                 \
        }                                                                          \
        CPA_COMMIT();                                                              \
    } while (0)

    // prologue: stage 0 fills in flight
    FILL_STAGE(0);

    for (int s = 0; s < NS; s++) {
        int kc = s >> 1, out = s & 1, buf = s % 3;
        uint32_t bstu = sb + 32768 + buf * 65536;

        int sn = s + 1;
        if (sn < NS) {
            // before refilling buffer sn%3, its previous MMA user (stage sn-3)
            // must have committed
            if (sn >= 3) {
                int bn = sn % 3;
                int idx = (sn - 3 - bn) / 3;
                mbar_wait(cu + 8 + bn * 8, idx & 1);
            }
            FILL_STAGE(sn);
            CPA_WAIT1();  // stage s's group done; stage sn's stays in flight
        } else {
            CPA_WAIT0();
        }
        asm volatile("fence.proxy.async.shared::cta;" ::: "memory");
        __syncthreads();

        if (wid == 0 && elect1()) {
            uint64_t dA  = mk_desc(sb + (kc & 1) * 16384);
            uint64_t dBh = mk_desc(bstu);
            uint64_t dBl = mk_desc(bstu + loOfs);
            uint32_t D = tmem + out * 256;
#pragma unroll
            for (int k = 0; k < 4; k++) {
                uint64_t o = (uint64_t)(k * 2);
                mma_ss_f16(D, dA + o, dBh + o, idesc, (uint32_t)((kc | k) != 0));
                mma_ss_f16(D, dA + o, dBl + o, idesc, 1u);
            }
            asm volatile("tcgen05.commit.cta_group::1.mbarrier::arrive::one.shared::cluster.b64 [%0];"
                         :: "r"(cu + 8 + buf * 8) : "memory");
        }
        // NOTE: no __syncthreads here; next iteration's mbar_wait provides the
        // needed cross-stage ordering, and the fills target a different buffer.
    }
#undef FILL_STAGE

    for (int s = (NS >= 3 ? NS - 3 : 0); s < NS; s++) {
        int b = s % 3;
        int idx = (s - b) / 3;
        mbar_wait(cu + 8 + b * 8, idx & 1);
    }
    asm volatile("tcgen05.fence::after_thread_sync;" ::: "memory");

    int lane = tid & 31, sub = wid & 3, wg = wid >> 2;
    int m = m0 + sub * 32 + lane;
    int niter = Nout >> 5;
    uint32_t base = tmem + wg * 256;
    for (int cc = 0; cc < niter; cc++) {
        uint32_t r[32];
        LDTM32(r, base + cc * 32);
        asm volatile("tcgen05.wait::ld.sync.aligned;" ::: "memory");
        if (m < MTOT) {
            int nb = cc * 32;
            if (wg == 0) {
                if (yh16) {
                    uint32_t hp[16];
#pragma unroll
                    for (int q = 0; q < 16; q++)
                        hp[q] = pkh2(__uint_as_float(r[2 * q])     + bias[nb + 2 * q],
                                     __uint_as_float(r[2 * q + 1]) + bias[nb + 2 * q + 1]);
                    uint4* dp = reinterpret_cast<uint4*>((char*)yh16 + ((size_t)m * Nout + nb) * 2);
#pragma unroll
                    for (int q = 0; q < 4; q++)
                        dp[q] = make_uint4(hp[4 * q], hp[4 * q + 1], hp[4 * q + 2], hp[4 * q + 3]);
                } else {
                    float4* dp = reinterpret_cast<float4*>(yhf32 + (size_t)m * Nout + nb);
#pragma unroll
                    for (int q = 0; q < 8; q++) {
                        float4 v;
                        v.x = __uint_as_float(r[q * 4 + 0]) + bias[nb + q * 4 + 0];
                        v.y = __uint_as_float(r[q * 4 + 1]) + bias[nb + q * 4 + 1];
                        v.z = __uint_as_float(r[q * 4 + 2]) + bias[nb + q * 4 + 2];
                        v.w = __uint_as_float(r[q * 4 + 3]) + bias[nb + q * 4 + 3];
                        dp[q] = v;
                    }
                }
            } else {
                float dv = g_dinv[m];
                uint32_t hp[16];
#pragma unroll
                for (int q = 0; q < 16; q++)
                    hp[q] = pkh2(dv * __uint_as_float(r[2 * q]),
                                 dv * __uint_as_float(r[2 * q + 1]));
                uint4* dp = reinterpret_cast<uint4*>((char*)yx + ((size_t)m * Nout + nb) * 2);
#pragma unroll
                for (int q = 0; q < 4; q++)
                    dp[q] = make_uint4(hp[4 * q], hp[4 * q + 1], hp[4 * q + 2], hp[4 * q + 3]);
            }
        }
    }
    __syncthreads();
    if (wid == 0) {
        asm volatile("tcgen05.dealloc.cta_group::1.sync.aligned.b32 %0, %1;"
                     :: "r"(tmem), "r"(512u));
    }
#endif  // TC_OK
}

// ---------------- SIMT fallback GEMM (non-"a" passes only) -------------------
__global__ void __launch_bounds__(256) k_gemm_fb(
    const __half* __restrict__ act, int K,
    const __half* __restrict__ Whi, const __half* __restrict__ Wlo,
    const float* __restrict__ bias, int Nout, uint32_t idesc,
    float* __restrict__ yhf32, __half* __restrict__ yh16, __half* __restrict__ yx)
{
#if !TC_OK
    __shared__ float As[16][132];
    __shared__ float Bs[16][128];
    int tid = threadIdx.x;
    int tx = tid & 15, ty = tid >> 4;
    int m0 = blockIdx.x * 128;
    size_t hofs = (size_t)blockIdx.y * Nout * K;
    const __half* Bh = Whi + hofs;
    const __half* Bl = Wlo + hofs;

    for (int n0 = 0; n0 < Nout; n0 += 128) {
        float acc[8][8];
#pragma unroll
        for (int i = 0; i < 8; i++)
#pragma unroll
            for (int j = 0; j < 8; j++) acc[i][j] = 0.f;

        for (int k0 = 0; k0 < K; k0 += 16) {
            for (int i = tid; i < 2048; i += 256) {
                int r = i >> 4, k = i & 15;
                int m = m0 + r;
                As[k][r] = (m < MTOT) ? __half2float(act[(size_t)m * K + k0 + k]) : 0.f;
            }
            for (int i = tid; i < 2048; i += 256) {
                int r = i >> 4, k = i & 15;
                size_t o = (size_t)(n0 + r) * K + k0 + k;
                Bs[k][r] = __half2float(Bh[o]) + __half2float(Bl[o]);
            }
            __syncthreads();
#pragma unroll
            for (int k = 0; k < 16; k++) {
                float a[8], b[8];
#pragma unroll
                for (int i = 0; i < 8; i++) a[i] = As[k][ty * 8 + i];
#pragma unroll
                for (int j = 0; j < 8; j++) b[j] = Bs[k][tx * 8 + j];
#pragma unroll
                for (int i = 0; i < 8; i++)
#pragma unroll
                    for (int j = 0; j < 8; j++) acc[i][j] += a[i] * b[j];
            }
            __syncthreads();
        }

#pragma unroll
        for (int i = 0; i < 8; i++) {
            int m = m0 + ty * 8 + i;
            if (m >= MTOT) continue;
            float dv = g_dinv[m];
#pragma unroll
            for (int j = 0; j < 8; j++) {
                int n = n0 + tx * 8 + j;
                if (blockIdx.y == 0) {
                    float v = acc[i][j] + bias[n];
                    if (yh16) yh16[(size_t)m * Nout + n] = __float2half_rn(v);
                    else      yhf32[(size_t)m * Nout + n] = v;
                } else {
                    yx[(size_t)m * Nout + n] = __float2half_rn(dv * acc[i][j]);
                }
            }
        }
        __syncthreads();
    }
#endif  // !TC_OK
}

// ---------------- launch -----------------------------------------------------
static inline uint32_t mk_idesc(int N) {
    return (1u << 4) | ((uint32_t)(N / 8) << 17) | (8u << 24);
}

extern "C" void kernel_launch(void* const* d_in, const int* in_sizes, int n_in,
                              void* d_out, int out_size) {
    const float* x   = (const float*)d_in[0];
    const int*   src = (const int*)d_in[1];
    const int*   dst = (const int*)d_in[2];
    const float* W1  = (const float*)d_in[3];
    const float* b1  = (const float*)d_in[4];
    const float* W2  = (const float*)d_in[5];
    const float* b2  = (const float*)d_in[6];
    const float* W3  = (const float*)d_in[7];
    const float* b3  = (const float*)d_in[8];
    float* out = (float*)d_out;

    void* p;
    cudaGetSymbolAddress(&p, g_act);  __half* act  = (__half*)p;
    cudaGetSymbolAddress(&p, g_yh);   float*  yhf  = (float*)p;
    __half* yhh = (__half*)yhf;
    cudaGetSymbolAddress(&p, g_yx);   __half* yx   = (__half*)p;
    cudaGetSymbolAddress(&p, g_Whi);  __half* Whi  = (__half*)p;
    cudaGetSymbolAddress(&p, g_Wlo);  __half* Wlo  = (__half*)p;
    void* degp; cudaGetSymbolAddress(&degp, g_deg);

    cudaFuncSetAttribute(k_gemm_tc, cudaFuncAttributeMaxDynamicSharedMemorySize, 231424);

    static cudaStream_t s2 = nullptr;
    static cudaEvent_t evFork = nullptr, evJoin = nullptr;
    if (!s2) {
        cudaStreamCreateWithFlags(&s2, cudaStreamNonBlocking);
        cudaEventCreateWithFlags(&evFork, cudaEventDisableTiming);
        cudaEventCreateWithFlags(&evJoin, cudaEventDisableTiming);
    }

    uint32_t id256 = mk_idesc(256), id128 = mk_idesc(128);
    int gg = (MTOT + 127) / 128;     // 391
    dim3 ggfb(gg, 2);
    int gs = (MTOT + 7) / 8;         // 6250
    size_t shm = 231424;

    auto gemm = [&](int K, const __half* bh, const __half* bl,
                    const float* bias, int Nout, uint32_t idesc, __half* y16) {
        k_gemm_tc<<<gg, 256, shm>>>(act, K, bh, bl, bias, Nout, idesc,
                                    y16 ? nullptr : yhf, y16, yx);
        k_gemm_fb<<<ggfb, 256>>>(act, K, bh, bl, bias, Nout, idesc,
                                 y16 ? nullptr : yhf, y16, yx);
    };

    // ---- fork: CSR build + W2/W3 conversion on s2  ||  W1+X conv + L1 GEMM on main ----
    cudaEventRecord(evFork, 0);
    cudaStreamWaitEvent(s2, evFork, 0);

    int nblk = (MTOT + 1023) / 1024;  // 49
    cudaMemsetAsync(degp, 0, MTOT * sizeof(int), s2);
    k_count<<<(NE + 255) / 256, 256, 0, s2>>>(dst);
    k_scan1<<<nblk, 1024, 0, s2>>>();
    k_scan2<<<1, 64, 0, s2>>>(nblk);
    k_scan3<<<nblk, 1024, 0, s2>>>();
    k_scatter<<<(NE + 255) / 256, 256, 0, s2>>>(src, dst);
    k_convW2<<<(512 * 256 + 255) / 256, 256, 0, s2>>>(W2, 256, 256, Whi + 65536, Wlo + 65536);
    k_convW2<<<(512 * 128 + 255) / 256, 256, 0, s2>>>(W3, 256, 128, Whi + 196608, Wlo + 196608);
    cudaEventRecord(evJoin, s2);

    // main stream: W1 conversion + input conversion + L1 GEMM (no CSR dependency)
    k_convW2<<<(256 * 256 + 255) / 256, 256>>>(W1, 128, 256, Whi, Wlo);
    k_convX<<<(MTOT * 32 + 255) / 256, 256>>>(x, act);
    gemm(128, Whi, Wlo, b1, 256, id256, yhh);

    // join: L1 agg needs CSR
    cudaStreamWaitEvent(0, evJoin, 0);
    k_aggact<8, 1, 1><<<gs, 256>>>(yhh, yx, 256, act, nullptr);

    // L2-4: K=256, Nout=256 (shared W2), fp16 yh
    for (int l = 0; l < 3; l++) {
        gemm(256, Whi + 65536, Wlo + 65536, b2, 256, id256, yhh);
        k_aggact<8, 1, 1><<<gs, 256>>>(yhh, yx, 256, act, nullptr);
    }
    // L5: K=256, Nout=128; fp32 yh, final out, no tanh
    gemm(256, Whi + 196608, Wlo + 196608, b3, 128, id128, nullptr);
    k_aggact<4, 0, 0><<<gs, 256>>>(yhf, yx, 128, nullptr, out);
}

// round 14
// speedup vs baseline: 2.4602x; 1.0111x over previous
#include <cuda_runtime.h>
#include <cuda_bf16.h>
#include <cuda_fp16.h>
#include <stdint.h>
#include <math.h>

#define MTOT 50000
#define NE   800000

#if defined(__CUDA_ARCH_FEAT_SM103_ALL) || defined(__CUDA_ARCH_FEAT_SM100_ALL) || \
    defined(__CUDA_ARCH_FEAT_SM101_ALL) || defined(__CUDA_ARCH_FEAT_SM110_ALL)
#define TC_OK 1
#else
#define TC_OK 0
#endif

#if defined(__CUDA_ARCH__) && (__CUDA_ARCH__ >= 900)
#define PDL_WAIT()       asm volatile("griddepcontrol.wait;" ::: "memory")
#define PDL_LAUNCH_DEP() asm volatile("griddepcontrol.launch_dependents;" ::: "memory")
#else
#define PDL_WAIT()
#define PDL_LAUNCH_DEP()
#endif

// ---------------- device scratch (no cudaMalloc) ----------------------------
__device__ __align__(16) __half g_act[(size_t)MTOT * 256];
__device__ __align__(16) float  g_yh[(size_t)MTOT * 256];   // fp32 L5; fp16 view L1-4
__device__ __align__(16) __half g_yx[(size_t)MTOT * 256];
__device__ __align__(16) __half g_Whi[262144];
__device__ __align__(16) __half g_Wlo[262144];
__device__ float g_dinv[MTOT];
__device__ int   g_deg[MTOT];
__device__ int   g_off[MTOT + 1];
__device__ int   g_cur[MTOT];
__device__ int   g_csrc[NE];
__device__ int   g_bsum[64];

// ---------------- small helpers ---------------------------------------------
__device__ __forceinline__ uint32_t smem_u32(const void* p) {
    uint32_t a;
    asm("{ .reg .u64 t; cvta.to.shared.u64 t, %1; cvt.u32.u64 %0, t; }" : "=r"(a) : "l"(p));
    return a;
}
__device__ __forceinline__ bool elect1() {
    uint32_t p;
    asm volatile("{\n\t.reg .pred p;\n\telect.sync _|p, 0xFFFFFFFF;\n\tselp.b32 %0,1,0,p;\n\t}" : "=r"(p));
    return p != 0;
}
__device__ __forceinline__ void mbar_init(uint32_t mbar, uint32_t cnt) {
    asm volatile("mbarrier.init.shared.b64 [%0], %1;" :: "r"(mbar), "r"(cnt) : "memory");
}
__device__ __forceinline__ void mbar_wait(uint32_t mbar, uint32_t parity) {
    uint32_t done;
    asm volatile("{\n\t.reg .pred p;\n\tmbarrier.try_wait.parity.acquire.cta.shared::cta.b64 p, [%1], %2;\n\tselp.b32 %0,1,0,p;\n\t}"
                 : "=r"(done) : "r"(mbar), "r"(parity) : "memory");
    if (!done) {
        asm volatile("{\n\t.reg .pred P1;\nWL_%=:\n\tmbarrier.try_wait.parity.acquire.cta.shared::cta.b64 P1, [%0], %1, 0x989680;\n\t@P1 bra.uni WD_%=;\n\tbra.uni WL_%=;\nWD_%=:\n\t}"
                     :: "r"(mbar), "r"(parity) : "memory");
    }
}
__device__ __forceinline__ float tanha(float x) {
    float y; asm("tanh.approx.f32 %0, %1;" : "=f"(y) : "f"(x)); return y;
}
__device__ __forceinline__ uint32_t pkh2(float a, float b) {
    __half2 h = __floats2half2_rn(a, b);
    return *reinterpret_cast<uint32_t*>(&h);
}
#define CPA16(sm_u32, gptr) \
    asm volatile("cp.async.cg.shared.global [%0], [%1], 16;" :: "r"(sm_u32), "l"(gptr) : "memory")
#define CPA_COMMIT() asm volatile("cp.async.commit_group;" ::: "memory")
#define CPA_WAIT0()  asm volatile("cp.async.wait_group 0;" ::: "memory")
#define CPA_WAIT1()  asm volatile("cp.async.wait_group 1;" ::: "memory")

#if TC_OK
__device__ __forceinline__ uint64_t mk_desc(uint32_t addr) {
    // SW128, version=1(Blackwell), SBO=64, LBO=1, start=addr>>4
    return 0x4000404000010000ULL | ((uint64_t)(addr >> 4) & 0x3FFF);
}
__device__ __forceinline__ void mma_ss_f16(uint32_t d, uint64_t ad, uint64_t bd,
                                           uint32_t idesc, uint32_t en) {
    asm volatile("{\n\t.reg .pred p;\n\tsetp.ne.u32 p, %4, 0;\n\t"
                 "tcgen05.mma.cta_group::1.kind::f16 [%0], %1, %2, %3, {%5,%5,%5,%5}, p;\n\t}"
                 :: "r"(d), "l"(ad), "l"(bd), "r"(idesc), "r"(en), "r"(0u) : "memory");
}
#define LDTM32(r, addr) \
    asm volatile("tcgen05.ld.sync.aligned.32x32b.x32.b32 " \
        "{%0,%1,%2,%3,%4,%5,%6,%7,%8,%9,%10,%11,%12,%13,%14,%15," \
        "%16,%17,%18,%19,%20,%21,%22,%23,%24,%25,%26,%27,%28,%29,%30,%31}, [%32];" \
        : "=r"((r)[0]),"=r"((r)[1]),"=r"((r)[2]),"=r"((r)[3]),"=r"((r)[4]),"=r"((r)[5]),"=r"((r)[6]),"=r"((r)[7]), \
          "=r"((r)[8]),"=r"((r)[9]),"=r"((r)[10]),"=r"((r)[11]),"=r"((r)[12]),"=r"((r)[13]),"=r"((r)[14]),"=r"((r)[15]), \
          "=r"((r)[16]),"=r"((r)[17]),"=r"((r)[18]),"=r"((r)[19]),"=r"((r)[20]),"=r"((r)[21]),"=r"((r)[22]),"=r"((r)[23]), \
          "=r"((r)[24]),"=r"((r)[25]),"=r"((r)[26]),"=r"((r)[27]),"=r"((r)[28]),"=r"((r)[29]),"=r"((r)[30]),"=r"((r)[31]) \
        : "r"(addr))
#endif

// ---------------- CSR build (parallel scan) ----------------------------------
__global__ void k_count(const int* __restrict__ dst) {
    int e = blockIdx.x * blockDim.x + threadIdx.x;
    if (e < NE) atomicAdd(&g_deg[dst[e]], 1);
}
__global__ void k_scan1() {
    __shared__ int sh[1024];
    int t = threadIdx.x;
    int i = blockIdx.x * 1024 + t;
    int v = (i < MTOT) ? g_deg[i] : 0;
    sh[t] = v;
    __syncthreads();
    for (int ofs = 1; ofs < 1024; ofs <<= 1) {
        int x = (t >= ofs) ? sh[t - ofs] : 0;
        __syncthreads();
        sh[t] += x;
        __syncthreads();
    }
    if (i < MTOT) g_off[i] = sh[t] - v;
    if (t == 1023) g_bsum[blockIdx.x] = sh[1023];
}
__global__ void k_scan2(int nblk) {
    __shared__ int sh[64];
    int t = threadIdx.x;
    int v = (t < nblk) ? g_bsum[t] : 0;
    sh[t] = v;
    __syncthreads();
    for (int ofs = 1; ofs < 64; ofs <<= 1) {
        int x = (t >= ofs) ? sh[t - ofs] : 0;
        __syncthreads();
        sh[t] += x;
        __syncthreads();
    }
    if (t < nblk) g_bsum[t] = sh[t] - v;
}
__global__ void k_scan3() {
    int i = blockIdx.x * 1024 + threadIdx.x;
    if (i < MTOT) {
        int o = g_off[i] + g_bsum[i >> 10];
        g_off[i] = o;
        g_cur[i] = o;
        int d = g_deg[i];
        g_dinv[i] = (d > 0) ? rsqrtf((float)d) : 0.0f;
    }
    if (i == 0) g_off[MTOT] = NE;
}
__global__ void k_scatter(const int* __restrict__ src, const int* __restrict__ dst) {
    int e = blockIdx.x * blockDim.x + threadIdx.x;
    if (e < NE) {
        int p = atomicAdd(&g_cur[dst[e]], 1);
        g_csrc[p] = src[e];
    }
}

// ---------------- converters ------------------------------------------------
__global__ void k_convW2(const float* __restrict__ W, int F, int N,
                         __half* __restrict__ oh, __half* __restrict__ ol) {
    int idx = blockIdx.x * blockDim.x + threadIdx.x;
    if (idx >= 2 * F * N) return;
    int k2 = idx / N, n = idx % N;
    int half = (k2 >= F);
    int k = k2 - half * F;
    float v = W[(size_t)k2 * N + n];
    __half h = __float2half_rn(v);
    size_t o = (size_t)half * N * F + (size_t)n * F + k;
    oh[o] = h;
    ol[o] = __float2half_rn(v - __half2float(h));
}

__global__ void k_convX(const float* __restrict__ x, __half* __restrict__ act) {
    int idx = blockIdx.x * blockDim.x + threadIdx.x;
    if (idx >= MTOT * 32) return;
    int m = idx >> 5, c4 = (idx & 31) << 2;
    float4 v = *reinterpret_cast<const float4*>(x + (size_t)m * 128 + c4);
    uint2 p;
    p.x = pkh2(v.x, v.y);
    p.y = pkh2(v.z, v.w);
    *reinterpret_cast<uint2*>((char*)act + ((size_t)m * 128 + c4) * 2) = p;
}

// ---------------- aggregation + activation ----------------------------------
template <int CPL, int ACT, int YH16>
__global__ void k_aggact(const void* __restrict__ yhp, const __half* __restrict__ yx,
                         int Nout, __half* __restrict__ oact, float* __restrict__ of32) {
    PDL_WAIT();
    int node = blockIdx.x * 8 + (threadIdx.x >> 5);
    if (node >= MTOT) return;
    int lane = threadIdx.x & 31;
    int col = lane * CPL;
    float acc[CPL];
#pragma unroll
    for (int i = 0; i < CPL; i++) acc[i] = 0.f;
    int e0 = g_off[node], e1 = g_off[node + 1];
    const char* yxb = (const char*)yx;
    int e = e0;

    if constexpr (CPL == 8) {
        for (; e + 4 <= e1; e += 4) {
            int j0 = g_csrc[e], j1 = g_csrc[e + 1], j2 = g_csrc[e + 2], j3 = g_csrc[e + 3];
            uint4 p0 = *reinterpret_cast<const uint4*>(yxb + ((size_t)j0 * Nout + col) * 2);
            uint4 p1 = *reinterpret_cast<const uint4*>(yxb + ((size_t)j1 * Nout + col) * 2);
            uint4 p2 = *reinterpret_cast<const uint4*>(yxb + ((size_t)j2 * Nout + col) * 2);
            uint4 p3 = *reinterpret_cast<const uint4*>(yxb + ((size_t)j3 * Nout + col) * 2);
            uint32_t w0[4] = {p0.x, p0.y, p0.z, p0.w};
            uint32_t w1[4] = {p1.x, p1.y, p1.z, p1.w};
            uint32_t w2[4] = {p2.x, p2.y, p2.z, p2.w};
            uint32_t w3[4] = {p3.x, p3.y, p3.z, p3.w};
#pragma unroll
            for (int q = 0; q < 4; q++) {
                float2 f0 = __half22float2(*reinterpret_cast<__half2*>(&w0[q]));
                float2 f1 = __half22float2(*reinterpret_cast<__half2*>(&w1[q]));
                float2 f2 = __half22float2(*reinterpret_cast<__half2*>(&w2[q]));
                float2 f3 = __half22float2(*reinterpret_cast<__half2*>(&w3[q]));
                acc[2 * q]     += (f0.x + f1.x) + (f2.x + f3.x);
                acc[2 * q + 1] += (f0.y + f1.y) + (f2.y + f3.y);
            }
        }
        for (; e < e1; e++) {
            int j0 = g_csrc[e];
            uint4 p0 = *reinterpret_cast<const uint4*>(yxb + ((size_t)j0 * Nout + col) * 2);
            uint32_t w0[4] = {p0.x, p0.y, p0.z, p0.w};
#pragma unroll
            for (int q = 0; q < 4; q++) {
                float2 f0 = __half22float2(*reinterpret_cast<__half2*>(&w0[q]));
                acc[2 * q] += f0.x; acc[2 * q + 1] += f0.y;
            }
        }
    } else {
        for (; e + 4 <= e1; e += 4) {
            int j0 = g_csrc[e], j1 = g_csrc[e + 1], j2 = g_csrc[e + 2], j3 = g_csrc[e + 3];
            uint2 p0 = *reinterpret_cast<const uint2*>(yxb + ((size_t)j0 * Nout + col) * 2);
            uint2 p1 = *reinterpret_cast<const uint2*>(yxb + ((size_t)j1 * Nout + col) * 2);
            uint2 p2 = *reinterpret_cast<const uint2*>(yxb + ((size_t)j2 * Nout + col) * 2);
            uint2 p3 = *reinterpret_cast<const uint2*>(yxb + ((size_t)j3 * Nout + col) * 2);
            uint32_t w0[2] = {p0.x, p0.y};
            uint32_t w1[2] = {p1.x, p1.y};
            uint32_t w2[2] = {p2.x, p2.y};
            uint32_t w3[2] = {p3.x, p3.y};
#pragma unroll
            for (int q = 0; q < 2; q++) {
                float2 f0 = __half22float2(*reinterpret_cast<__half2*>(&w0[q]));
                float2 f1 = __half22float2(*reinterpret_cast<__half2*>(&w1[q]));
                float2 f2 = __half22float2(*reinterpret_cast<__half2*>(&w2[q]));
                float2 f3 = __half22float2(*reinterpret_cast<__half2*>(&w3[q]));
                acc[2 * q]     += (f0.x + f1.x) + (f2.x + f3.x);
                acc[2 * q + 1] += (f0.y + f1.y) + (f2.y + f3.y);
            }
        }
        for (; e < e1; e++) {
            int j0 = g_csrc[e];
            uint2 p0 = *reinterpret_cast<const uint2*>(yxb + ((size_t)j0 * Nout + col) * 2);
            uint32_t w0[2] = {p0.x, p0.y};
#pragma unroll
            for (int q = 0; q < 2; q++) {
                float2 f0 = __half22float2(*reinterpret_cast<__half2*>(&w0[q]));
                acc[2 * q] += f0.x; acc[2 * q + 1] += f0.y;
            }
        }
    }

    float dv = g_dinv[node];
    float v[CPL];
    if constexpr (YH16) {
        const char* yhb = (const char*)yhp;
        if constexpr (CPL == 8) {
            uint4 y = *reinterpret_cast<const uint4*>(yhb + ((size_t)node * Nout + col) * 2);
            uint32_t yw[4] = {y.x, y.y, y.z, y.w};
#pragma unroll
            for (int q = 0; q < 4; q++) {
                float2 f = __half22float2(*reinterpret_cast<__half2*>(&yw[q]));
                v[2 * q]     = f.x - dv * acc[2 * q];
                v[2 * q + 1] = f.y - dv * acc[2 * q + 1];
            }
        } else {
            uint2 y = *reinterpret_cast<const uint2*>(yhb + ((size_t)node * Nout + col) * 2);
            uint32_t yw[2] = {y.x, y.y};
#pragma unroll
            for (int q = 0; q < 2; q++) {
                float2 f = __half22float2(*reinterpret_cast<__half2*>(&yw[q]));
                v[2 * q]     = f.x - dv * acc[2 * q];
                v[2 * q + 1] = f.y - dv * acc[2 * q + 1];
            }
        }
    } else {
        const float* yh = (const float*)yhp;
#pragma unroll
        for (int i = 0; i < CPL; i += 4) {
            float4 y = *reinterpret_cast<const float4*>(yh + (size_t)node * Nout + col + i);
            v[i + 0] = y.x - dv * acc[i + 0];
            v[i + 1] = y.y - dv * acc[i + 1];
            v[i + 2] = y.z - dv * acc[i + 2];
            v[i + 3] = y.w - dv * acc[i + 3];
        }
    }
    if constexpr (ACT) {
#pragma unroll
        for (int i = 0; i < CPL; i++) v[i] = tanha(v[i]);
        size_t wo = ((size_t)node * Nout + col) * 2;
        if constexpr (CPL == 8) {
            uint4 p;
            p.x = pkh2(v[0], v[1]); p.y = pkh2(v[2], v[3]);
            p.z = pkh2(v[4], v[5]); p.w = pkh2(v[6], v[7]);
            *reinterpret_cast<uint4*>((char*)oact + wo) = p;
        } else {
            uint2 p;
            p.x = pkh2(v[0], v[1]); p.y = pkh2(v[2], v[3]);
            *reinterpret_cast<uint2*>((char*)oact + wo) = p;
        }
    } else {
#pragma unroll
        for (int i = 0; i < CPL; i += 4) {
            float4 o = make_float4(v[i], v[i + 1], v[i + 2], v[i + 3]);
            *reinterpret_cast<float4*>(of32 + (size_t)node * Nout + col + i) = o;
        }
    }
    PDL_LAUNCH_DEP();
}

// ---------------- tcgen05 dual-output fp16 GEMM ------------------------------
// One CTA = 128 rows; yh = act@Wh + b (TMEM [0,256)), yx = dinv*(act@Wx) ([256,512)).
// Software-pipelined; PDL wait before first global read, launch_dependents after stores.
__global__ void __launch_bounds__(256, 1) k_gemm_tc(
    const __half* __restrict__ act, int K,
    const __half* __restrict__ Whi, const __half* __restrict__ Wlo,
    const float* __restrict__ bias, int Nout, uint32_t idesc,
    float* __restrict__ yhf32, __half* __restrict__ yh16, __half* __restrict__ yx)
{
#if TC_OK
    extern __shared__ char smraw[];
    __shared__ __align__(16) uint32_t ctrl[8];  // [0]=tmem ptr; mbars at +8,+16,+24
    int tid = threadIdx.x, wid = tid >> 5;
    uint32_t cu = smem_u32(ctrl);

    if (wid == 0) {
        asm volatile("tcgen05.alloc.cta_group::1.sync.aligned.shared::cta.b32 [%0], %1;"
                     :: "r"(cu), "r"(512u) : "memory");
        asm volatile("tcgen05.relinquish_alloc_permit.cta_group::1.sync.aligned;");
    }
    if (tid == 0) { mbar_init(cu + 8, 1); mbar_init(cu + 16, 1); mbar_init(cu + 24, 1); }
    __syncthreads();
    uint32_t tmem;
    asm("ld.shared.b32 %0, [%1];" : "=r"(tmem) : "r"(cu));

    uint32_t raw = smem_u32(smraw);
    uint32_t sb = (raw + 1023) & ~1023u;
    char* sm = smraw + (sb - raw);

    int m0 = blockIdx.x * 128;
    const char* Ab = (const char*)act;
    int NS = (K >> 6) * 2;
    int nbB = Nout << 3;
    int loOfs = Nout << 7;

    PDL_WAIT();  // predecessor's act/weights must be visible before fills

#define FILL_STAGE(S)                                                              \
    do {                                                                           \
        int kc_ = (S) >> 1, out_ = (S) & 1, buf_ = (S) % 3;                        \
        uint32_t bstu_ = sb + 32768 + buf_ * 65536;                                \
        if (out_ == 0) {                                                           \
            uint32_t astu_ = sb + (kc_ & 1) * 16384;                               \
            char* ast_ = sm + (kc_ & 1) * 16384;                                   \
            for (int i = tid; i < 1024; i += 256) {                                \
                int row_ = i >> 3, c_ = i & 7;                                     \
                int m_ = m0 + row_;                                                \
                uint32_t bo_ = (row_ << 7) + (c_ << 4);                            \
                uint32_t so_ = bo_ ^ ((bo_ >> 3) & 0x70);                          \
                if (m_ < MTOT) {                                                   \
                    CPA16(astu_ + so_, Ab + ((size_t)m_ * K + (kc_ << 6) + (c_ << 3)) * 2); \
                } else {                                                           \
                    *reinterpret_cast<uint4*>(ast_ + so_) = make_uint4(0, 0, 0, 0);\
                }                                                                  \
            }                                                                      \
        }                                                                          \
        size_t wofs_ = (size_t)out_ * Nout * K;                                    \
        const char* Bh_ = (const char*)(Whi + wofs_);                              \
        const char* Bl_ = (const char*)(Wlo + wofs_);                              \
        for (int i = tid; i < nbB; i += 256) {                                     \
            int n_ = i >> 3, c_ = i & 7;                                           \
            size_t go_ = ((size_t)n_ * K + (kc_ << 6) + (c_ << 3)) * 2;            \
            uint32_t bo_ = (n_ << 7) + (c_ << 4);                                  \
            uint32_t so_ = bo_ ^ ((bo_ >> 3) & 0x70);                              \
            CPA16(bstu_ + so_, Bh_ + go_);                                         \
            CPA16(bstu_ + loOfs + so_, Bl_ + go_);                                 \
        }                                                                          \
        CPA_COMMIT();                                                              \
    } while (0)

    FILL_STAGE(0);

    for (int s = 0; s < NS; s++) {
        int kc = s >> 1, out = s & 1, buf = s % 3;
        uint32_t bstu = sb + 32768 + buf * 65536;

        int sn = s + 1;
        if (sn < NS) {
            if (sn >= 3) {
                int bn = sn % 3;
                int idx = (sn - 3 - bn) / 3;
                mbar_wait(cu + 8 + bn * 8, idx & 1);
            }
            FILL_STAGE(sn);
            CPA_WAIT1();
        } else {
            CPA_WAIT0();
        }
        asm volatile("fence.proxy.async.shared::cta;" ::: "memory");
        __syncthreads();

        if (wid == 0 && elect1()) {
            uint64_t dA  = mk_desc(sb + (kc & 1) * 16384);
            uint64_t dBh = mk_desc(bstu);
            uint64_t dBl = mk_desc(bstu + loOfs);
            uint32_t D = tmem + out * 256;
#pragma unroll
            for (int k = 0; k < 4; k++) {
                uint64_t o = (uint64_t)(k * 2);
                mma_ss_f16(D, dA + o, dBh + o, idesc, (uint32_t)((kc | k) != 0));
                mma_ss_f16(D, dA + o, dBl + o, idesc, 1u);
            }
            asm volatile("tcgen05.commit.cta_group::1.mbarrier::arrive::one.shared::cluster.b64 [%0];"
                         :: "r"(cu + 8 + buf * 8) : "memory");
        }
    }
#undef FILL_STAGE

    for (int s = (NS >= 3 ? NS - 3 : 0); s < NS; s++) {
        int b = s % 3;
        int idx = (s - b) / 3;
        mbar_wait(cu + 8 + b * 8, idx & 1);
    }
    asm volatile("tcgen05.fence::after_thread_sync;" ::: "memory");

    int lane = tid & 31, sub = wid & 3, wg = wid >> 2;
    int m = m0 + sub * 32 + lane;
    int niter = Nout >> 5;
    uint32_t base = tmem + wg * 256;
    for (int cc = 0; cc < niter; cc++) {
        uint32_t r[32];
        LDTM32(r, base + cc * 32);
        asm volatile("tcgen05.wait::ld.sync.aligned;" ::: "memory");
        if (m < MTOT) {
            int nb = cc * 32;
            if (wg == 0) {
                if (yh16) {
                    uint32_t hp[16];
#pragma unroll
                    for (int q = 0; q < 16; q++)
                        hp[q] = pkh2(__uint_as_float(r[2 * q])     + bias[nb + 2 * q],
                                     __uint_as_float(r[2 * q + 1]) + bias[nb + 2 * q + 1]);
                    uint4* dp = reinterpret_cast<uint4*>((char*)yh16 + ((size_t)m * Nout + nb) * 2);
#pragma unroll
                    for (int q = 0; q < 4; q++)
                        dp[q] = make_uint4(hp[4 * q], hp[4 * q + 1], hp[4 * q + 2], hp[4 * q + 3]);
                } else {
                    float4* dp = reinterpret_cast<float4*>(yhf32 + (size_t)m * Nout + nb);
#pragma unroll
                    for (int q = 0; q < 8; q++) {
                        float4 v;
                        v.x = __uint_as_float(r[q * 4 + 0]) + bias[nb + q * 4 + 0];
                        v.y = __uint_as_float(r[q * 4 + 1]) + bias[nb + q * 4 + 1];
                        v.z = __uint_as_float(r[q * 4 + 2]) + bias[nb + q * 4 + 2];
                        v.w = __uint_as_float(r[q * 4 + 3]) + bias[nb + q * 4 + 3];
                        dp[q] = v;
                    }
                }
            } else {
                float dv = g_dinv[m];
                uint32_t hp[16];
#pragma unroll
                for (int q = 0; q < 16; q++)
                    hp[q] = pkh2(dv * __uint_as_float(r[2 * q]),
                                 dv * __uint_as_float(r[2 * q + 1]));
                uint4* dp = reinterpret_cast<uint4*>((char*)yx + ((size_t)m * Nout + nb) * 2);
#pragma unroll
                for (int q = 0; q < 4; q++)
                    dp[q] = make_uint4(hp[4 * q], hp[4 * q + 1], hp[4 * q + 2], hp[4 * q + 3]);
            }
        }
    }
    PDL_LAUNCH_DEP();
    __syncthreads();
    if (wid == 0) {
        asm volatile("tcgen05.dealloc.cta_group::1.sync.aligned.b32 %0, %1;"
                     :: "r"(tmem), "r"(512u));
    }
#endif  // TC_OK
}

// ---------------- SIMT fallback GEMM (kept for non-"a" compile; NOT launched) -
__global__ void __launch_bounds__(256) k_gemm_fb(
    const __half* __restrict__ act, int K,
    const __half* __restrict__ Whi, const __half* __restrict__ Wlo,
    const float* __restrict__ bias, int Nout, uint32_t idesc,
    float* __restrict__ yhf32, __half* __restrict__ yh16, __half* __restrict__ yx)
{
#if !TC_OK
    // unreachable on GB300 (sm_103a cubin path is live); body retained so the
    // plain compute_103 PTX pass has a complete translation unit.
    int tid = blockIdx.x * blockDim.x + threadIdx.x;
    if (tid == 0 && act && Whi && Wlo && bias) {
        if (yh16) yh16[0] = __float2half_rn(0.f);
    }
#endif
}

// ---------------- launch helpers ---------------------------------------------
template <typename... A>
static void pdl_launch(void (*k)(A...), dim3 g, dim3 b, size_t shm, A... args) {
    cudaLaunchConfig_t cfg = {};
    cfg.gridDim = g;
    cfg.blockDim = b;
    cfg.dynamicSmemBytes = shm;
    cfg.stream = 0;
    cudaLaunchAttribute at[1];
    at[0].id = cudaLaunchAttributeProgrammaticStreamSerialization;
    at[0].val.programmaticStreamSerializationAllowed = 1;
    cfg.attrs = at;
    cfg.numAttrs = 1;
    cudaLaunchKernelEx(&cfg, k, args...);
}

static inline uint32_t mk_idesc(int N) {
    return (1u << 4) | ((uint32_t)(N / 8) << 17) | (8u << 24);
}

extern "C" void kernel_launch(void* const* d_in, const int* in_sizes, int n_in,
                              void* d_out, int out_size) {
    const float* x   = (const float*)d_in[0];
    const int*   src = (const int*)d_in[1];
    const int*   dst = (const int*)d_in[2];
    const float* W1  = (const float*)d_in[3];
    const float* b1  = (const float*)d_in[4];
    const float* W2  = (const float*)d_in[5];
    const float* b2  = (const float*)d_in[6];
    const float* W3  = (const float*)d_in[7];
    const float* b3  = (const float*)d_in[8];
    float* out = (float*)d_out;

    void* p;
    cudaGetSymbolAddress(&p, g_act);  __half* act  = (__half*)p;
    cudaGetSymbolAddress(&p, g_yh);   float*  yhf  = (float*)p;
    __half* yhh = (__half*)yhf;
    cudaGetSymbolAddress(&p, g_yx);   __half* yx   = (__half*)p;
    cudaGetSymbolAddress(&p, g_Whi);  __half* Whi  = (__half*)p;
    cudaGetSymbolAddress(&p, g_Wlo);  __half* Wlo  = (__half*)p;
    void* degp; cudaGetSymbolAddress(&degp, g_deg);

    cudaFuncSetAttribute(k_gemm_tc, cudaFuncAttributeMaxDynamicSharedMemorySize, 231424);

    static cudaStream_t s2 = nullptr;
    static cudaEvent_t evFork = nullptr, evJoin = nullptr;
    if (!s2) {
        cudaStreamCreateWithFlags(&s2, cudaStreamNonBlocking);
        cudaEventCreateWithFlags(&evFork, cudaEventDisableTiming);
        cudaEventCreateWithFlags(&evJoin, cudaEventDisableTiming);
    }

    uint32_t id256 = mk_idesc(256), id128 = mk_idesc(128);
    int gg = (MTOT + 127) / 128;     // 391
    int gs = (MTOT + 7) / 8;         // 6250
    size_t shm = 231424;

    auto gemm = [&](int K, const __half* bh, const __half* bl,
                    const float* bias, int Nout, uint32_t idesc, __half* y16) {
        pdl_launch(k_gemm_tc, dim3(gg), dim3(256), shm,
                   (const __half*)act, K, bh, bl, bias, Nout, idesc,
                   (float*)(y16 ? nullptr : yhf), y16, (__half*)yx);
    };
    auto agg = [&](__half* y16src, int Nout, __half* oact) {
        pdl_launch(k_aggact<8, 1, 1>, dim3(gs), dim3(256), (size_t)0,
                   (const void*)y16src, (const __half*)yx, Nout,
                   (__half*)oact, (float*)nullptr);
    };

    // ---- fork: CSR build + W2/W3 conversion on s2  ||  W1+X conv + L1 GEMM on main ----
    cudaEventRecord(evFork, 0);
    cudaStreamWaitEvent(s2, evFork, 0);

    int nblk = (MTOT + 1023) / 1024;  // 49
    cudaMemsetAsync(degp, 0, MTOT * sizeof(int), s2);
    k_count<<<(NE + 255) / 256, 256, 0, s2>>>(dst);
    k_scan1<<<nblk, 1024, 0, s2>>>();
    k_scan2<<<1, 64, 0, s2>>>(nblk);
    k_scan3<<<nblk, 1024, 0, s2>>>();
    k_scatter<<<(NE + 255) / 256, 256, 0, s2>>>(src, dst);
    k_convW2<<<(512 * 256 + 255) / 256, 256, 0, s2>>>(W2, 256, 256, Whi + 65536, Wlo + 65536);
    k_convW2<<<(512 * 128 + 255) / 256, 256, 0, s2>>>(W3, 256, 128, Whi + 196608, Wlo + 196608);
    cudaEventRecord(evJoin, s2);

    // main stream: W1 conversion + input conversion + L1 GEMM (no CSR dependency)
    k_convW2<<<(256 * 256 + 255) / 256, 256>>>(W1, 128, 256, Whi, Wlo);
    k_convX<<<(MTOT * 32 + 255) / 256, 256>>>(x, act);
    gemm(128, Whi, Wlo, b1, 256, id256, yhh);

    // join: L1 agg needs CSR
    cudaStreamWaitEvent(0, evJoin, 0);
    agg(yhh, 256, act);

    // L2-4: K=256, Nout=256 (shared W2), fp16 yh
    for (int l = 0; l < 3; l++) {
        gemm(256, Whi + 65536, Wlo + 65536, b2, 256, id256, yhh);
        agg(yhh, 256, act);
    }
    // L5: K=256, Nout=128; fp32 yh, final out, no tanh
    gemm(256, Whi + 196608, Wlo + 196608, b3, 128, id128, nullptr);
    pdl_launch(k_aggact<4, 0, 0>, dim3(gs), dim3(256), (size_t)0,
               (const void*)yhf, (const __half*)yx, 128,
               (__half*)nullptr, (float*)out);
}

// round 15
// speedup vs baseline: 2.4824x; 1.0090x over previous
#include <cuda_runtime.h>
#include <cuda_bf16.h>
#include <cuda_fp16.h>
#include <stdint.h>
#include <math.h>

#define MTOT 50000
#define NE   800000

#if defined(__CUDA_ARCH_FEAT_SM103_ALL) || defined(__CUDA_ARCH_FEAT_SM100_ALL) || \
    defined(__CUDA_ARCH_FEAT_SM101_ALL) || defined(__CUDA_ARCH_FEAT_SM110_ALL)
#define TC_OK 1
#else
#define TC_OK 0
#endif

#if defined(__CUDA_ARCH__) && (__CUDA_ARCH__ >= 900)
#define PDL_WAIT()       asm volatile("griddepcontrol.wait;" ::: "memory")
#define PDL_LAUNCH_DEP() asm volatile("griddepcontrol.launch_dependents;" ::: "memory")
#else
#define PDL_WAIT()
#define PDL_LAUNCH_DEP()
#endif

// ---------------- device scratch (no cudaMalloc) ----------------------------
__device__ __align__(16) __half g_act[(size_t)MTOT * 256];
__device__ __align__(16) float  g_yh[(size_t)MTOT * 256];   // fp32 L5; fp16 view L1-4
__device__ __align__(16) __half g_yx[(size_t)MTOT * 256];
__device__ __align__(16) __half g_Whi[262144];
__device__ __align__(16) __half g_Wlo[262144];
__device__ float g_dinv[MTOT];
__device__ int   g_deg[MTOT];
__device__ int   g_off[MTOT + 1];
__device__ int   g_cur[MTOT];
__device__ int   g_csrc[NE];
__device__ int   g_bsum[64];

// ---------------- small helpers ---------------------------------------------
__device__ __forceinline__ uint32_t smem_u32(const void* p) {
    uint32_t a;
    asm("{ .reg .u64 t; cvta.to.shared.u64 t, %1; cvt.u32.u64 %0, t; }" : "=r"(a) : "l"(p));
    return a;
}
__device__ __forceinline__ bool elect1() {
    uint32_t p;
    asm volatile("{\n\t.reg .pred p;\n\telect.sync _|p, 0xFFFFFFFF;\n\tselp.b32 %0,1,0,p;\n\t}" : "=r"(p));
    return p != 0;
}
__device__ __forceinline__ void mbar_init(uint32_t mbar, uint32_t cnt) {
    asm volatile("mbarrier.init.shared.b64 [%0], %1;" :: "r"(mbar), "r"(cnt) : "memory");
}
__device__ __forceinline__ void mbar_wait(uint32_t mbar, uint32_t parity) {
    uint32_t done;
    asm volatile("{\n\t.reg .pred p;\n\tmbarrier.try_wait.parity.acquire.cta.shared::cta.b64 p, [%1], %2;\n\tselp.b32 %0,1,0,p;\n\t}"
                 : "=r"(done) : "r"(mbar), "r"(parity) : "memory");
    if (!done) {
        asm volatile("{\n\t.reg .pred P1;\nWL_%=:\n\tmbarrier.try_wait.parity.acquire.cta.shared::cta.b64 P1, [%0], %1, 0x989680;\n\t@P1 bra.uni WD_%=;\n\tbra.uni WL_%=;\nWD_%=:\n\t}"
                     :: "r"(mbar), "r"(parity) : "memory");
    }
}
__device__ __forceinline__ float tanha(float x) {
    float y; asm("tanh.approx.f32 %0, %1;" : "=f"(y) : "f"(x)); return y;
}
__device__ __forceinline__ uint32_t pkh2(float a, float b) {
    __half2 h = __floats2half2_rn(a, b);
    return *reinterpret_cast<uint32_t*>(&h);
}
#define CPA16(sm_u32, gptr) \
    asm volatile("cp.async.cg.shared.global [%0], [%1], 16;" :: "r"(sm_u32), "l"(gptr) : "memory")
#define CPA_COMMIT() asm volatile("cp.async.commit_group;" ::: "memory")
#define CPA_WAIT0()  asm volatile("cp.async.wait_group 0;" ::: "memory")
#define CPA_WAIT1()  asm volatile("cp.async.wait_group 1;" ::: "memory")

#if TC_OK
__device__ __forceinline__ uint64_t mk_desc(uint32_t addr) {
    // SW128, version=1(Blackwell), SBO=64, LBO=1, start=addr>>4
    return 0x4000404000010000ULL | ((uint64_t)(addr >> 4) & 0x3FFF);
}
__device__ __forceinline__ void mma_ss_f16(uint32_t d, uint64_t ad, uint64_t bd,
                                           uint32_t idesc, uint32_t en) {
    asm volatile("{\n\t.reg .pred p;\n\tsetp.ne.u32 p, %4, 0;\n\t"
                 "tcgen05.mma.cta_group::1.kind::f16 [%0], %1, %2, %3, {%5,%5,%5,%5}, p;\n\t}"
                 :: "r"(d), "l"(ad), "l"(bd), "r"(idesc), "r"(en), "r"(0u) : "memory");
}
#define LDTM32(r, addr) \
    asm volatile("tcgen05.ld.sync.aligned.32x32b.x32.b32 " \
        "{%0,%1,%2,%3,%4,%5,%6,%7,%8,%9,%10,%11,%12,%13,%14,%15," \
        "%16,%17,%18,%19,%20,%21,%22,%23,%24,%25,%26,%27,%28,%29,%30,%31}, [%32];" \
        : "=r"((r)[0]),"=r"((r)[1]),"=r"((r)[2]),"=r"((r)[3]),"=r"((r)[4]),"=r"((r)[5]),"=r"((r)[6]),"=r"((r)[7]), \
          "=r"((r)[8]),"=r"((r)[9]),"=r"((r)[10]),"=r"((r)[11]),"=r"((r)[12]),"=r"((r)[13]),"=r"((r)[14]),"=r"((r)[15]), \
          "=r"((r)[16]),"=r"((r)[17]),"=r"((r)[18]),"=r"((r)[19]),"=r"((r)[20]),"=r"((r)[21]),"=r"((r)[22]),"=r"((r)[23]), \
          "=r"((r)[24]),"=r"((r)[25]),"=r"((r)[26]),"=r"((r)[27]),"=r"((r)[28]),"=r"((r)[29]),"=r"((r)[30]),"=r"((r)[31]) \
        : "r"(addr))
#endif

// ---------------- CSR build (parallel scan) ----------------------------------
__global__ void k_count(const int* __restrict__ dst) {
    int e = blockIdx.x * blockDim.x + threadIdx.x;
    if (e < NE) atomicAdd(&g_deg[dst[e]], 1);
}
__global__ void k_scan1() {
    __shared__ int sh[1024];
    int t = threadIdx.x;
    int i = blockIdx.x * 1024 + t;
    int v = (i < MTOT) ? g_deg[i] : 0;
    sh[t] = v;
    __syncthreads();
    for (int ofs = 1; ofs < 1024; ofs <<= 1) {
        int x = (t >= ofs) ? sh[t - ofs] : 0;
        __syncthreads();
        sh[t] += x;
        __syncthreads();
    }
    if (i < MTOT) g_off[i] = sh[t] - v;
    if (t == 1023) g_bsum[blockIdx.x] = sh[1023];
}
__global__ void k_scan2(int nblk) {
    __shared__ int sh[64];
    int t = threadIdx.x;
    int v = (t < nblk) ? g_bsum[t] : 0;
    sh[t] = v;
    __syncthreads();
    for (int ofs = 1; ofs < 64; ofs <<= 1) {
        int x = (t >= ofs) ? sh[t - ofs] : 0;
        __syncthreads();
        sh[t] += x;
        __syncthreads();
    }
    if (t < nblk) g_bsum[t] = sh[t] - v;
}
__global__ void k_scan3() {
    int i = blockIdx.x * 1024 + threadIdx.x;
    if (i < MTOT) {
        int o = g_off[i] + g_bsum[i >> 10];
        g_off[i] = o;
        g_cur[i] = o;
        int d = g_deg[i];
        g_dinv[i] = (d > 0) ? rsqrtf((float)d) : 0.0f;
    }
    if (i == 0) g_off[MTOT] = NE;
}
__global__ void k_scatter(const int* __restrict__ src, const int* __restrict__ dst) {
    int e = blockIdx.x * blockDim.x + threadIdx.x;
    if (e < NE) {
        int p = atomicAdd(&g_cur[dst[e]], 1);
        g_csrc[p] = src[e];
    }
}

// ---------------- converters ------------------------------------------------
__global__ void k_convW2(const float* __restrict__ W, int F, int N,
                         __half* __restrict__ oh, __half* __restrict__ ol) {
    int idx = blockIdx.x * blockDim.x + threadIdx.x;
    if (idx >= 2 * F * N) return;
    int k2 = idx / N, n = idx % N;
    int half = (k2 >= F);
    int k = k2 - half * F;
    float v = W[(size_t)k2 * N + n];
    __half h = __float2half_rn(v);
    size_t o = (size_t)half * N * F + (size_t)n * F + k;
    oh[o] = h;
    ol[o] = __float2half_rn(v - __half2float(h));
}

__global__ void k_convX(const float* __restrict__ x, __half* __restrict__ act) {
    int idx = blockIdx.x * blockDim.x + threadIdx.x;
    if (idx >= MTOT * 32) return;
    int m = idx >> 5, c4 = (idx & 31) << 2;
    float4 v = *reinterpret_cast<const float4*>(x + (size_t)m * 128 + c4);
    uint2 p;
    p.x = pkh2(v.x, v.y);
    p.y = pkh2(v.z, v.w);
    *reinterpret_cast<uint2*>((char*)act + ((size_t)m * 128 + c4) * 2) = p;
}

// ---------------- aggregation + activation ----------------------------------
template <int CPL, int ACT, int YH16>
__global__ void k_aggact(const void* __restrict__ yhp, const __half* __restrict__ yx,
                         int Nout, __half* __restrict__ oact, float* __restrict__ of32) {
    PDL_WAIT();
    int node = blockIdx.x * 8 + (threadIdx.x >> 5);
    if (node >= MTOT) return;
    int lane = threadIdx.x & 31;
    int col = lane * CPL;
    float acc[CPL];
#pragma unroll
    for (int i = 0; i < CPL; i++) acc[i] = 0.f;
    int e0 = g_off[node], e1 = g_off[node + 1];
    const char* yxb = (const char*)yx;
    int e = e0;

    if constexpr (CPL == 8) {
        for (; e + 4 <= e1; e += 4) {
            int j0 = g_csrc[e], j1 = g_csrc[e + 1], j2 = g_csrc[e + 2], j3 = g_csrc[e + 3];
            uint4 p0 = *reinterpret_cast<const uint4*>(yxb + ((size_t)j0 * Nout + col) * 2);
            uint4 p1 = *reinterpret_cast<const uint4*>(yxb + ((size_t)j1 * Nout + col) * 2);
            uint4 p2 = *reinterpret_cast<const uint4*>(yxb + ((size_t)j2 * Nout + col) * 2);
            uint4 p3 = *reinterpret_cast<const uint4*>(yxb + ((size_t)j3 * Nout + col) * 2);
            uint32_t w0[4] = {p0.x, p0.y, p0.z, p0.w};
            uint32_t w1[4] = {p1.x, p1.y, p1.z, p1.w};
            uint32_t w2[4] = {p2.x, p2.y, p2.z, p2.w};
            uint32_t w3[4] = {p3.x, p3.y, p3.z, p3.w};
#pragma unroll
            for (int q = 0; q < 4; q++) {
                float2 f0 = __half22float2(*reinterpret_cast<__half2*>(&w0[q]));
                float2 f1 = __half22float2(*reinterpret_cast<__half2*>(&w1[q]));
                float2 f2 = __half22float2(*reinterpret_cast<__half2*>(&w2[q]));
                float2 f3 = __half22float2(*reinterpret_cast<__half2*>(&w3[q]));
                acc[2 * q]     += (f0.x + f1.x) + (f2.x + f3.x);
                acc[2 * q + 1] += (f0.y + f1.y) + (f2.y + f3.y);
            }
        }
        for (; e < e1; e++) {
            int j0 = g_csrc[e];
            uint4 p0 = *reinterpret_cast<const uint4*>(yxb + ((size_t)j0 * Nout + col) * 2);
            uint32_t w0[4] = {p0.x, p0.y, p0.z, p0.w};
#pragma unroll
            for (int q = 0; q < 4; q++) {
                float2 f0 = __half22float2(*reinterpret_cast<__half2*>(&w0[q]));
                acc[2 * q] += f0.x; acc[2 * q + 1] += f0.y;
            }
        }
    } else {
        for (; e + 4 <= e1; e += 4) {
            int j0 = g_csrc[e], j1 = g_csrc[e + 1], j2 = g_csrc[e + 2], j3 = g_csrc[e + 3];
            uint2 p0 = *reinterpret_cast<const uint2*>(yxb + ((size_t)j0 * Nout + col) * 2);
            uint2 p1 = *reinterpret_cast<const uint2*>(yxb + ((size_t)j1 * Nout + col) * 2);
            uint2 p2 = *reinterpret_cast<const uint2*>(yxb + ((size_t)j2 * Nout + col) * 2);
            uint2 p3 = *reinterpret_cast<const uint2*>(yxb + ((size_t)j3 * Nout + col) * 2);
            uint32_t w0[2] = {p0.x, p0.y};
            uint32_t w1[2] = {p1.x, p1.y};
            uint32_t w2[2] = {p2.x, p2.y};
            uint32_t w3[2] = {p3.x, p3.y};
#pragma unroll
            for (int q = 0; q < 2; q++) {
                float2 f0 = __half22float2(*reinterpret_cast<__half2*>(&w0[q]));
                float2 f1 = __half22float2(*reinterpret_cast<__half2*>(&w1[q]));
                float2 f2 = __half22float2(*reinterpret_cast<__half2*>(&w2[q]));
                float2 f3 = __half22float2(*reinterpret_cast<__half2*>(&w3[q]));
                acc[2 * q]     += (f0.x + f1.x) + (f2.x + f3.x);
                acc[2 * q + 1] += (f0.y + f1.y) + (f2.y + f3.y);
            }
        }
        for (; e < e1; e++) {
            int j0 = g_csrc[e];
            uint2 p0 = *reinterpret_cast<const uint2*>(yxb + ((size_t)j0 * Nout + col) * 2);
            uint32_t w0[2] = {p0.x, p0.y};
#pragma unroll
            for (int q = 0; q < 2; q++) {
                float2 f0 = __half22float2(*reinterpret_cast<__half2*>(&w0[q]));
                acc[2 * q] += f0.x; acc[2 * q + 1] += f0.y;
            }
        }
    }

    float dv = g_dinv[node];
    float v[CPL];
    if constexpr (YH16) {
        const char* yhb = (const char*)yhp;
        if constexpr (CPL == 8) {
            uint4 y = *reinterpret_cast<const uint4*>(yhb + ((size_t)node * Nout + col) * 2);
            uint32_t yw[4] = {y.x, y.y, y.z, y.w};
#pragma unroll
            for (int q = 0; q < 4; q++) {
                float2 f = __half22float2(*reinterpret_cast<__half2*>(&yw[q]));
                v[2 * q]     = f.x - dv * acc[2 * q];
                v[2 * q + 1] = f.y - dv * acc[2 * q + 1];
            }
        } else {
            uint2 y = *reinterpret_cast<const uint2*>(yhb + ((size_t)node * Nout + col) * 2);
            uint32_t yw[2] = {y.x, y.y};
#pragma unroll
            for (int q = 0; q < 2; q++) {
                float2 f = __half22float2(*reinterpret_cast<__half2*>(&yw[q]));
                v[2 * q]     = f.x - dv * acc[2 * q];
                v[2 * q + 1] = f.y - dv * acc[2 * q + 1];
            }
        }
    } else {
        const float* yh = (const float*)yhp;
#pragma unroll
        for (int i = 0; i < CPL; i += 4) {
            float4 y = *reinterpret_cast<const float4*>(yh + (size_t)node * Nout + col + i);
            v[i + 0] = y.x - dv * acc[i + 0];
            v[i + 1] = y.y - dv * acc[i + 1];
            v[i + 2] = y.z - dv * acc[i + 2];
            v[i + 3] = y.w - dv * acc[i + 3];
        }
    }
    if constexpr (ACT) {
#pragma unroll
        for (int i = 0; i < CPL; i++) v[i] = tanha(v[i]);
        size_t wo = ((size_t)node * Nout + col) * 2;
        if constexpr (CPL == 8) {
            uint4 p;
            p.x = pkh2(v[0], v[1]); p.y = pkh2(v[2], v[3]);
            p.z = pkh2(v[4], v[5]); p.w = pkh2(v[6], v[7]);
            *reinterpret_cast<uint4*>((char*)oact + wo) = p;
        } else {
            uint2 p;
            p.x = pkh2(v[0], v[1]); p.y = pkh2(v[2], v[3]);
            *reinterpret_cast<uint2*>((char*)oact + wo) = p;
        }
    } else {
#pragma unroll
        for (int i = 0; i < CPL; i += 4) {
            float4 o = make_float4(v[i], v[i + 1], v[i + 2], v[i + 3]);
            *reinterpret_cast<float4*>(of32 + (size_t)node * Nout + col + i) = o;
        }
    }
    PDL_LAUNCH_DEP();
}

// ---------------- tcgen05 dual-output fp16 GEMM (N-split, 2 CTAs/SM) ---------
// grid (391, 2): blockIdx.y = h selects N-slice [h*S, (h+1)*S), S = Nout/2.
// CTA computes yh and yx for its slice. TMEM 256 cols/CTA (yh [0,S), yx [S,2S)).
// SMEM 97KB: A slots 2x16KB @0/@16K; B 2 bufs x 32KB @32K/@64K (hi + lo@S*128).
__global__ void __launch_bounds__(256, 2) k_gemm_tc(
    const __half* __restrict__ act, int K,
    const __half* __restrict__ Whi, const __half* __restrict__ Wlo,
    const float* __restrict__ bias, int Nout, uint32_t idesc,
    float* __restrict__ yhf32, __half* __restrict__ yh16, __half* __restrict__ yx)
{
#if TC_OK
    extern __shared__ char smraw[];
    __shared__ __align__(16) uint32_t ctrl[8];  // [0]=tmem ptr; mbars at +8,+16
    int tid = threadIdx.x, wid = tid >> 5;
    uint32_t cu = smem_u32(ctrl);

    if (wid == 0) {
        asm volatile("tcgen05.alloc.cta_group::1.sync.aligned.shared::cta.b32 [%0], %1;"
                     :: "r"(cu), "r"(256u) : "memory");
        asm volatile("tcgen05.relinquish_alloc_permit.cta_group::1.sync.aligned;");
    }
    if (tid == 0) { mbar_init(cu + 8, 1); mbar_init(cu + 16, 1); }
    __syncthreads();
    uint32_t tmem;
    asm("ld.shared.b32 %0, [%1];" : "=r"(tmem) : "r"(cu));

    uint32_t raw = smem_u32(smraw);
    uint32_t sb = (raw + 1023) & ~1023u;
    char* sm = smraw + (sb - raw);

    int m0 = blockIdx.x * 128;
    int h = blockIdx.y;
    int S = Nout >> 1;
    const char* Ab = (const char*)act;
    int NS = (K >> 6) * 2;
    int nbB = S << 3;          // uint4s per B part tile
    int loOfs = S << 7;        // bytes: S*128 (hi tile size)

    PDL_WAIT();

#define FILL_STAGE(SS)                                                             \
    do {                                                                           \
        int kc_ = (SS) >> 1, out_ = (SS) & 1, buf_ = (SS) & 1;                     \
        uint32_t bstu_ = sb + 32768 + buf_ * 32768;                                \
        if (out_ == 0) {                                                           \
            uint32_t astu_ = sb + (kc_ & 1) * 16384;                               \
            char* ast_ = sm + (kc_ & 1) * 16384;                                   \
            for (int i = tid; i < 1024; i += 256) {                                \
                int row_ = i >> 3, c_ = i & 7;                                     \
                int m_ = m0 + row_;                                                \
                uint32_t bo_ = (row_ << 7) + (c_ << 4);                            \
                uint32_t so_ = bo_ ^ ((bo_ >> 3) & 0x70);                          \
                if (m_ < MTOT) {                                                   \
                    CPA16(astu_ + so_, Ab + ((size_t)m_ * K + (kc_ << 6) + (c_ << 3)) * 2); \
                } else {                                                           \
                    *reinterpret_cast<uint4*>(ast_ + so_) = make_uint4(0, 0, 0, 0);\
                }                                                                  \
            }                                                                      \
        }                                                                          \
        size_t wofs_ = (size_t)out_ * Nout * K + (size_t)h * S * K;                \
        const char* Bh_ = (const char*)(Whi + wofs_);                              \
        const char* Bl_ = (const char*)(Wlo + wofs_);                              \
        for (int i = tid; i < nbB; i += 256) {                                     \
            int n_ = i >> 3, c_ = i & 7;                                           \
            size_t go_ = ((size_t)n_ * K + (kc_ << 6) + (c_ << 3)) * 2;            \
            uint32_t bo_ = (n_ << 7) + (c_ << 4);                                  \
            uint32_t so_ = bo_ ^ ((bo_ >> 3) & 0x70);                              \
            CPA16(bstu_ + so_, Bh_ + go_);                                         \
            CPA16(bstu_ + loOfs + so_, Bl_ + go_);                                 \
        }                                                                          \
        CPA_COMMIT();                                                              \
    } while (0)

    FILL_STAGE(0);

    for (int s = 0; s < NS; s++) {
        int kc = s >> 1, out = s & 1, buf = s & 1;
        uint32_t bstu = sb + 32768 + buf * 32768;

        int sn = s + 1;
        if (sn < NS) {
            if (sn >= 2) {
                // buffer sn&1 was last used by stage sn-2; wait its commit
                int idx = (sn >> 1) - 1;
                mbar_wait(cu + 8 + (sn & 1) * 8, idx & 1);
            }
            FILL_STAGE(sn);
            CPA_WAIT1();
        } else {
            CPA_WAIT0();
        }
        asm volatile("fence.proxy.async.shared::cta;" ::: "memory");
        __syncthreads();

        if (wid == 0 && elect1()) {
            uint64_t dA  = mk_desc(sb + (kc & 1) * 16384);
            uint64_t dBh = mk_desc(bstu);
            uint64_t dBl = mk_desc(bstu + loOfs);
            uint32_t D = tmem + out * S;
#pragma unroll
            for (int k = 0; k < 4; k++) {
                uint64_t o = (uint64_t)(k * 2);
                mma_ss_f16(D, dA + o, dBh + o, idesc, (uint32_t)((kc | k) != 0));
                mma_ss_f16(D, dA + o, dBl + o, idesc, 1u);
            }
            asm volatile("tcgen05.commit.cta_group::1.mbarrier::arrive::one.shared::cluster.b64 [%0];"
                         :: "r"(cu + 8 + buf * 8) : "memory");
        }
    }
#undef FILL_STAGE

    // drain last two stage commits
    for (int s = (NS >= 2 ? NS - 2 : 0); s < NS; s++) {
        int b = s & 1;
        mbar_wait(cu + 8 + b * 8, (s >> 1) & 1);
    }
    asm volatile("tcgen05.fence::after_thread_sync;" ::: "memory");

    int lane = tid & 31, sub = wid & 3, wg = wid >> 2;  // wg0 -> yh slice, wg1 -> yx slice
    int m = m0 + sub * 32 + lane;
    int niter = S >> 5;
    uint32_t base = tmem + wg * S;
    for (int cc = 0; cc < niter; cc++) {
        uint32_t r[32];
        LDTM32(r, base + cc * 32);
        asm volatile("tcgen05.wait::ld.sync.aligned;" ::: "memory");
        if (m < MTOT) {
            int nb = h * S + cc * 32;   // global column base
            if (wg == 0) {
                if (yh16) {
                    uint32_t hp[16];
#pragma unroll
                    for (int q = 0; q < 16; q++)
                        hp[q] = pkh2(__uint_as_float(r[2 * q])     + bias[nb + 2 * q],
                                     __uint_as_float(r[2 * q + 1]) + bias[nb + 2 * q + 1]);
                    uint4* dp = reinterpret_cast<uint4*>((char*)yh16 + ((size_t)m * Nout + nb) * 2);
#pragma unroll
                    for (int q = 0; q < 4; q++)
                        dp[q] = make_uint4(hp[4 * q], hp[4 * q + 1], hp[4 * q + 2], hp[4 * q + 3]);
                } else {
                    float4* dp = reinterpret_cast<float4*>(yhf32 + (size_t)m * Nout + nb);
#pragma unroll
                    for (int q = 0; q < 8; q++) {
                        float4 v;
                        v.x = __uint_as_float(r[q * 4 + 0]) + bias[nb + q * 4 + 0];
                        v.y = __uint_as_float(r[q * 4 + 1]) + bias[nb + q * 4 + 1];
                        v.z = __uint_as_float(r[q * 4 + 2]) + bias[nb + q * 4 + 2];
                        v.w = __uint_as_float(r[q * 4 + 3]) + bias[nb + q * 4 + 3];
                        dp[q] = v;
                    }
                }
            } else {
                float dv = g_dinv[m];
                uint32_t hp[16];
#pragma unroll
                for (int q = 0; q < 16; q++)
                    hp[q] = pkh2(dv * __uint_as_float(r[2 * q]),
                                 dv * __uint_as_float(r[2 * q + 1]));
                uint4* dp = reinterpret_cast<uint4*>((char*)yx + ((size_t)m * Nout + nb) * 2);
#pragma unroll
                for (int q = 0; q < 4; q++)
                    dp[q] = make_uint4(hp[4 * q], hp[4 * q + 1], hp[4 * q + 2], hp[4 * q + 3]);
            }
        }
    }
    PDL_LAUNCH_DEP();
    __syncthreads();
    if (wid == 0) {
        asm volatile("tcgen05.dealloc.cta_group::1.sync.aligned.b32 %0, %1;"
                     :: "r"(tmem), "r"(256u));
    }
#endif  // TC_OK
}

// ---------------- SIMT fallback GEMM (kept for non-"a" compile; NOT launched) -
__global__ void __launch_bounds__(256) k_gemm_fb(
    const __half* __restrict__ act, int K,
    const __half* __restrict__ Whi, const __half* __restrict__ Wlo,
    const float* __restrict__ bias, int Nout, uint32_t idesc,
    float* __restrict__ yhf32, __half* __restrict__ yh16, __half* __restrict__ yx)
{
#if !TC_OK
    int tid = blockIdx.x * blockDim.x + threadIdx.x;
    if (tid == 0 && act && Whi && Wlo && bias) {
        if (yh16) yh16[0] = __float2half_rn(0.f);
    }
#endif
}

// ---------------- launch helpers ---------------------------------------------
template <typename... A>
static void pdl_launch(void (*k)(A...), dim3 g, dim3 b, size_t shm, A... args) {
    cudaLaunchConfig_t cfg = {};
    cfg.gridDim = g;
    cfg.blockDim = b;
    cfg.dynamicSmemBytes = shm;
    cfg.stream = 0;
    cudaLaunchAttribute at[1];
    at[0].id = cudaLaunchAttributeProgrammaticStreamSerialization;
    at[0].val.programmaticStreamSerializationAllowed = 1;
    cfg.attrs = at;
    cfg.numAttrs = 1;
    cudaLaunchKernelEx(&cfg, k, args...);
}

static inline uint32_t mk_idesc(int N) {
    return (1u << 4) | ((uint32_t)(N / 8) << 17) | (8u << 24);
}

extern "C" void kernel_launch(void* const* d_in, const int* in_sizes, int n_in,
                              void* d_out, int out_size) {
    const float* x   = (const float*)d_in[0];
    const int*   src = (const int*)d_in[1];
    const int*   dst = (const int*)d_in[2];
    const float* W1  = (const float*)d_in[3];
    const float* b1  = (const float*)d_in[4];
    const float* W2  = (const float*)d_in[5];
    const float* b2  = (const float*)d_in[6];
    const float* W3  = (const float*)d_in[7];
    const float* b3  = (const float*)d_in[8];
    float* out = (float*)d_out;

    void* p;
    cudaGetSymbolAddress(&p, g_act);  __half* act  = (__half*)p;
    cudaGetSymbolAddress(&p, g_yh);   float*  yhf  = (float*)p;
    __half* yhh = (__half*)yhf;
    cudaGetSymbolAddress(&p, g_yx);   __half* yx   = (__half*)p;
    cudaGetSymbolAddress(&p, g_Whi);  __half* Whi  = (__half*)p;
    cudaGetSymbolAddress(&p, g_Wlo);  __half* Wlo  = (__half*)p;
    void* degp; cudaGetSymbolAddress(&degp, g_deg);

    size_t shm = 99328;  // 32KB A + 2x32KB B + pad
    cudaFuncSetAttribute(k_gemm_tc, cudaFuncAttributeMaxDynamicSharedMemorySize, shm);

    static cudaStream_t s2 = nullptr;
    static cudaEvent_t evFork = nullptr, evJoin = nullptr;
    if (!s2) {
        cudaStreamCreateWithFlags(&s2, cudaStreamNonBlocking);
        cudaEventCreateWithFlags(&evFork, cudaEventDisableTiming);
        cudaEventCreateWithFlags(&evJoin, cudaEventDisableTiming);
    }

    uint32_t id128 = mk_idesc(128), id64 = mk_idesc(64);  // per-slice N
    int gg = (MTOT + 127) / 128;     // 391
    int gs = (MTOT + 7) / 8;         // 6250

    auto gemm = [&](int K, const __half* bh, const __half* bl,
                    const float* bias, int Nout, uint32_t idesc_slice, __half* y16) {
        pdl_launch(k_gemm_tc, dim3(gg, 2), dim3(256), shm,
                   (const __half*)act, K, bh, bl, bias, Nout, idesc_slice,
                   (float*)(y16 ? nullptr : yhf), y16, (__half*)yx);
    };
    auto agg = [&](__half* y16src, int Nout, __half* oact) {
        pdl_launch(k_aggact<8, 1, 1>, dim3(gs), dim3(256), (size_t)0,
                   (const void*)y16src, (const __half*)yx, Nout,
                   (__half*)oact, (float*)nullptr);
    };

    // ---- fork: CSR build + W2/W3 conversion on s2  ||  W1+X conv + L1 GEMM on main ----
    cudaEventRecord(evFork, 0);
    cudaStreamWaitEvent(s2, evFork, 0);

    int nblk = (MTOT + 1023) / 1024;  // 49
    cudaMemsetAsync(degp, 0, MTOT * sizeof(int), s2);
    k_count<<<(NE + 255) / 256, 256, 0, s2>>>(dst);
    k_scan1<<<nblk, 1024, 0, s2>>>();
    k_scan2<<<1, 64, 0, s2>>>(nblk);
    k_scan3<<<nblk, 1024, 0, s2>>>();
    k_scatter<<<(NE + 255) / 256, 256, 0, s2>>>(src, dst);
    k_convW2<<<(512 * 256 + 255) / 256, 256, 0, s2>>>(W2, 256, 256, Whi + 65536, Wlo + 65536);
    k_convW2<<<(512 * 128 + 255) / 256, 256, 0, s2>>>(W3, 256, 128, Whi + 196608, Wlo + 196608);
    cudaEventRecord(evJoin, s2);

    // main stream: W1 conversion + input conversion + L1 GEMM (no CSR dependency)
    k_convW2<<<(256 * 256 + 255) / 256, 256>>>(W1, 128, 256, Whi, Wlo);
    k_convX<<<(MTOT * 32 + 255) / 256, 256>>>(x, act);
    gemm(128, Whi, Wlo, b1, 256, id128, yhh);

    // join: L1 agg needs CSR
    cudaStreamWaitEvent(0, evJoin, 0);
    agg(yhh, 256, act);

    // L2-4: K=256, Nout=256 (shared W2), fp16 yh
    for (int l = 0; l < 3; l++) {
        gemm(256, Whi + 65536, Wlo + 65536, b2, 256, id128, yhh);
        agg(yhh, 256, act);
    }
    // L5: K=256, Nout=128; fp32 yh, final out, no tanh
    gemm(256, Whi + 196608, Wlo + 196608, b3, 128, id64, nullptr);
    pdl_launch(k_aggact<4, 0, 0>, dim3(gs), dim3(256), (size_t)0,
               (const void*)yhf, (const __half*)yx, 128,
               (__half*)nullptr, (float*)out);
}